// round 12
// baseline (speedup 1.0000x reference)
#include <cuda_runtime.h>
#include <math.h>
#include <cstdint>

// Problem constants
#define BB 4
#define TT 2048
#define CC 2048
#define HH 16
#define KVH 4
#define GG 4
#define DD 128
#define MROWS (BB*TT)          // 8192

#define BK 32
#define PADA 36     // A smem row pitch (words): 32 + 4
#define PADB 136    // B smem row pitch (words): 128 + 8
#define PADC 132    // C staging pitch (words)
#define KPITCH 132  // attention K smem pitch (16B-aligned, conflict-free)

// ---------------- scratch (device globals; allocation is forbidden) --------
__device__ float  g_q [(size_t)MROWS * (HH*DD)];
__device__ float  g_k [(size_t)MROWS * (KVH*DD)];
__device__ float  g_v [(size_t)MROWS * (KVH*DD)];
__device__ float  g_ao[(size_t)MROWS * (HH*DD)];
__device__ float2 g_cs[TT][64];                    // cos/sin(t * 10000^(-p/64))

// ---------------------------------------------------------------------------
// Angle table: fp32-rounded angle exactly as jnp would, then double trig.
// ---------------------------------------------------------------------------
__global__ void init_tables_kernel()
{
    int idx = blockIdx.x * blockDim.x + threadIdx.x;   // t*64 + p
    if (idx >= TT * 64) return;
    int t = idx >> 6;
    int p = idx & 63;

    double ex   = (double)p / 64.0;
    float  invf = (float)pow(10000.0, -ex);
    float  ang  = (float)t * invf;
    double c, s;
    sincos((double)ang, &c, &s);
    g_cs[t][p] = make_float2((float)c, (float)s);
}

__device__ __forceinline__ float f2tf32(float x)
{
    uint32_t u;
    asm("cvt.rna.tf32.f32 %0, %1;" : "=r"(u) : "f"(x));
    return __uint_as_float(u);
}

// ---------------------------------------------------------------------------
// tf32 tensor-core GEMM with fused REVERSED-RoPE epilogue (validated R9).
// 64x128 tile (M halved for 2 CTA/SM), BK=32, 256 threads (8 warps 4x2,
// warp tile 16x64). C staging UNIONED into As/Bs region (smem 53KB).
// ---------------------------------------------------------------------------
__global__ __launch_bounds__(256, 2) void gemm_tf32_rope_kernel(
    const float* __restrict__ A, const float* __restrict__ B,
    float* __restrict__ C, int M, int N, int K, int rope)
{
    extern __shared__ float sm[];
    float* As = sm;                                   // 2 * 64 * PADA  = 4608
    float* Bs = sm + 2 * 64 * PADA;                   // 2 * 32 * PADB  = 8704
    float* Cs = sm;                                   // union: 64*PADC = 8448

    const int tid  = threadIdx.x;
    const int lane = tid & 31;
    const int warp = tid >> 5;
    const int wm = warp >> 1;          // 0..3  (M, 16 rows each)
    const int wn = warp & 1;           // 0..1  (N, 64 cols each)
    const int bm = blockIdx.y * 64;
    const int bn = blockIdx.x * 128;

    const int nst = K / BK;

    float4 pa[2], pb[4];
    float acc[8][4];
#pragma unroll
    for (int nt = 0; nt < 8; nt++)
#pragma unroll
        for (int c = 0; c < 4; c++) acc[nt][c] = 0.f;

    // ---- prologue: stage 0 ----
    {
        const float* Ab = A + (size_t)bm * K;
        const float* Bb = B + bn;
#pragma unroll
        for (int j = 0; j < 2; j++) {            // A: 64x32 = 512 float4
            int ia = tid + j * 256;
            pa[j] = *(const float4*)(Ab + (size_t)(ia >> 3) * K + (ia & 7) * 4);
        }
#pragma unroll
        for (int j = 0; j < 4; j++) {            // B: 32x128 = 1024 float4
            int ib = tid + j * 256;
            pb[j] = *(const float4*)(Bb + (size_t)(ib >> 5) * N + (ib & 31) * 4);
        }
#pragma unroll
        for (int j = 0; j < 2; j++) {
            int ia = tid + j * 256;
            float* ap = As + (ia >> 3) * PADA + (ia & 7) * 4;
            *(float4*)ap = make_float4(f2tf32(pa[j].x), f2tf32(pa[j].y),
                                       f2tf32(pa[j].z), f2tf32(pa[j].w));
        }
#pragma unroll
        for (int j = 0; j < 4; j++) {
            int ib = tid + j * 256;
            float* bp = Bs + (ib >> 5) * PADB + (ib & 31) * 4;
            *(float4*)bp = make_float4(f2tf32(pb[j].x), f2tf32(pb[j].y),
                                       f2tf32(pb[j].z), f2tf32(pb[j].w));
        }
    }
    __syncthreads();

    for (int s = 0; s < nst; s++) {
        // ---- prefetch next stage into registers ----
        if (s + 1 < nst) {
            const float* Ab = A + (size_t)bm * K + (s + 1) * BK;
            const float* Bb = B + (size_t)(s + 1) * BK * N + bn;
#pragma unroll
            for (int j = 0; j < 2; j++) {
                int ia = tid + j * 256;
                pa[j] = *(const float4*)(Ab + (size_t)(ia >> 3) * K + (ia & 7) * 4);
            }
#pragma unroll
            for (int j = 0; j < 4; j++) {
                int ib = tid + j * 256;
                pb[j] = *(const float4*)(Bb + (size_t)(ib >> 5) * N + (ib & 31) * 4);
            }
        }

        // ---- compute on current buffer ----
        {
            const float* Ab = As + (s & 1) * 64 * PADA;
            const float* Bb = Bs + (s & 1) * 32 * PADB;
#pragma unroll
            for (int kk = 0; kk < 4; kk++) {
                uint32_t af[4], bf[8][2];
                const int k0 = kk * 8;
                const int arow = wm * 16 + (lane >> 2);
                const int acol = k0 + (lane & 3);
                {
                    const float* ap = Ab + (size_t)arow * PADA + acol;
                    af[0] = __float_as_uint(ap[0]);
                    af[1] = __float_as_uint(ap[8 * PADA]);
                    af[2] = __float_as_uint(ap[4]);
                    af[3] = __float_as_uint(ap[8 * PADA + 4]);
                }
                const int bk  = k0 + (lane & 3);
                const int bn0 = wn * 64 + (lane >> 2);
#pragma unroll
                for (int nt = 0; nt < 8; nt++) {
                    const float* bp = Bb + (size_t)bk * PADB + bn0 + nt * 8;
                    bf[nt][0] = __float_as_uint(bp[0]);
                    bf[nt][1] = __float_as_uint(bp[4 * PADB]);
                }
#pragma unroll
                for (int nt = 0; nt < 8; nt++)
                    asm volatile(
                        "mma.sync.aligned.m16n8k8.row.col.f32.tf32.tf32.f32 "
                        "{%0,%1,%2,%3}, {%4,%5,%6,%7}, {%8,%9}, {%0,%1,%2,%3};"
                        : "+f"(acc[nt][0]), "+f"(acc[nt][1]),
                          "+f"(acc[nt][2]), "+f"(acc[nt][3])
                        : "r"(af[0]), "r"(af[1]), "r"(af[2]), "r"(af[3]),
                          "r"(bf[nt][0]), "r"(bf[nt][1]));
            }
        }

        // ---- store prefetched stage into the other buffer ----
        if (s + 1 < nst) {
            float* Ad = As + ((s + 1) & 1) * 64 * PADA;
            float* Bd = Bs + ((s + 1) & 1) * 32 * PADB;
#pragma unroll
            for (int j = 0; j < 2; j++) {
                int ia = tid + j * 256;
                float* ap = Ad + (ia >> 3) * PADA + (ia & 7) * 4;
                *(float4*)ap = make_float4(f2tf32(pa[j].x), f2tf32(pa[j].y),
                                           f2tf32(pa[j].z), f2tf32(pa[j].w));
            }
#pragma unroll
            for (int j = 0; j < 4; j++) {
                int ib = tid + j * 256;
                float* bp = Bd + (ib >> 5) * PADB + (ib & 31) * 4;
                *(float4*)bp = make_float4(f2tf32(pb[j].x), f2tf32(pb[j].y),
                                           f2tf32(pb[j].z), f2tf32(pb[j].w));
            }
        }
        __syncthreads();
    }

    // ---- epilogue: stage through smem (Cs overlays As/Bs; mainloop done) --
    __syncthreads();
#pragma unroll
    for (int nt = 0; nt < 8; nt++) {
        int r0 = wm * 16 + (lane >> 2);
        int c0 = wn * 64 + nt * 8 + (lane & 3) * 2;
        *(float2*)&Cs[r0 * PADC + c0]       = make_float2(acc[nt][0], acc[nt][1]);
        *(float2*)&Cs[(r0 + 8) * PADC + c0] = make_float2(acc[nt][2], acc[nt][3]);
    }
    __syncthreads();

    if (rope) {
#pragma unroll
        for (int j = 0; j < 16; j++) {
            int idx = tid + j * 256;       // 64 rows * 64 pairs
            int row = idx >> 6, p = idx & 63;
            int t = (bm + row) & (TT - 1);
            float2 cs = g_cs[t][p];
            float a0 = Cs[row * PADC + p];
            float a1 = Cs[row * PADC + p + 64];
            float* crow = C + (size_t)(bm + row) * N + bn;
            crow[p]      = a0 * cs.x + a1 * cs.y;   // reversed rotation
            crow[p + 64] = a1 * cs.x - a0 * cs.y;
        }
    } else {
#pragma unroll
        for (int j = 0; j < 8; j++) {
            int idx = tid + j * 256;       // 64 rows * 32 float4
            int row = idx >> 5, c4 = idx & 31;
            *(float4*)(C + (size_t)(bm + row) * N + bn + c4 * 4) =
                *(float4*)&Cs[row * PADC + c4 * 4];
        }
    }
}

// ---------------------------------------------------------------------------
// Attention (causal, GQA), warp-private formulation.
// Round-12 change: K smem pitch 132 (16B-aligned) + float4 K loads
// (conflict-free: quarter-warp banks 4*lane+d all distinct) + vectorized
// tile loaders. Arithmetic identical to the validated kernel.
// smem: Q[64][128] | K[64][132] | V[64][128] | P[64][64]
// ---------------------------------------------------------------------------
__global__ __launch_bounds__(256) void attn_kernel(
    const float* __restrict__ q, const float* __restrict__ k,
    const float* __restrict__ v, float* __restrict__ o)
{
    extern __shared__ float smem[];
    float* sQ = smem;                       // 8192
    float* sK = sQ + 64 * 128;              // 64*KPITCH = 8448
    float* sV = sK + 64 * KPITCH;           // 8192
    float* sP = sV + 64 * 128;              // 4096

    const int qi = blockIdx.x;
    const int bh = blockIdx.y;
    const int b  = bh / HH;
    const int h  = bh % HH;
    const int kvh = h / GG;
    const int t0 = qi * 64;

    const int tid  = threadIdx.x;
    const int warp = tid >> 5;
    const int lane = tid & 31;

    const float scale = 0.08838834764831845f;

    // ---- load Q tile (pre-scaled), vectorized
#pragma unroll
    for (int j = 0; j < 8; j++) {
        int idx4 = tid + j * 256;           // 2048 float4
        int r = idx4 >> 5, c4 = idx4 & 31;
        float4 qv = *(const float4*)(q + (size_t)(b * TT + t0 + r) * (HH * DD) + h * DD + c4 * 4);
        qv.x *= scale; qv.y *= scale; qv.z *= scale; qv.w *= scale;
        *(float4*)&sQ[r * 128 + c4 * 4] = qv;
    }

    float m_i[8], l_i[8], oa[8][4];
#pragma unroll
    for (int rr = 0; rr < 8; rr++) {
        m_i[rr] = -1e30f; l_i[rr] = 0.f;
#pragma unroll
        for (int j = 0; j < 4; j++) oa[rr][j] = 0.f;
    }

    for (int jt = 0; jt <= qi; jt++) {
        __syncthreads();

        // ---- load K/V tiles, vectorized
#pragma unroll
        for (int j = 0; j < 8; j++) {
            int idx4 = tid + j * 256;
            int r = idx4 >> 5, c4 = idx4 & 31;
            size_t gofs = (size_t)(b * TT + jt * 64 + r) * (KVH * DD) + kvh * DD + c4 * 4;
            *(float4*)&sK[r * KPITCH + c4 * 4] = *(const float4*)(k + gofs);
            *(float4*)&sV[r * 128    + c4 * 4] = *(const float4*)(v + gofs);
        }
        __syncthreads();

#pragma unroll
        for (int rr = 0; rr < 8; rr++) {
            int r = warp * 8 + rr;
            const float* qrow = &sQ[r * 128];
            const float* k0p  = &sK[lane * KPITCH];
            const float* k1p  = &sK[(lane + 32) * KPITCH];
            float s0 = 0.f, s1 = 0.f;
#pragma unroll
            for (int d = 0; d < 128; d += 4) {
                float4 qv = *(const float4*)(qrow + d);
                float4 k0 = *(const float4*)(k0p + d);
                float4 k1 = *(const float4*)(k1p + d);
                s0 += qv.x * k0.x + qv.y * k0.y + qv.z * k0.z + qv.w * k0.w;
                s1 += qv.x * k1.x + qv.y * k1.y + qv.z * k1.z + qv.w * k1.w;
            }

            int qglob = t0 + r;
            if (jt * 64 + lane      > qglob) s0 = -1e30f;
            if (jt * 64 + lane + 32 > qglob) s1 = -1e30f;

            float mx = fmaxf(s0, s1);
#pragma unroll
            for (int off = 16; off >= 1; off >>= 1)
                mx = fmaxf(mx, __shfl_xor_sync(0xffffffffu, mx, off));

            float m_new = fmaxf(m_i[rr], mx);
            float p0 = __expf(s0 - m_new);
            float p1 = __expf(s1 - m_new);
            float rs = p0 + p1;
#pragma unroll
            for (int off = 16; off >= 1; off >>= 1)
                rs += __shfl_xor_sync(0xffffffffu, rs, off);

            float f = __expf(m_i[rr] - m_new);
            l_i[rr] = l_i[rr] * f + rs;
            m_i[rr] = m_new;
#pragma unroll
            for (int j = 0; j < 4; j++) oa[rr][j] *= f;

            sP[r * 64 + lane]      = p0;
            sP[r * 64 + lane + 32] = p1;
        }
        __syncwarp();

#pragma unroll
        for (int rr = 0; rr < 8; rr++) {
            int r = warp * 8 + rr;
            const float* prow = &sP[r * 64];
            float a0 = oa[rr][0], a1 = oa[rr][1], a2 = oa[rr][2], a3 = oa[rr][3];
#pragma unroll 4
            for (int c = 0; c < 64; c++) {
                float p = prow[c];
                float4 vv = *(const float4*)&sV[c * 128 + lane * 4];
                a0 += p * vv.x; a1 += p * vv.y; a2 += p * vv.z; a3 += p * vv.w;
            }
            oa[rr][0] = a0; oa[rr][1] = a1; oa[rr][2] = a2; oa[rr][3] = a3;
        }
    }

#pragma unroll
    for (int rr = 0; rr < 8; rr++) {
        int r = warp * 8 + rr;
        float invl = 1.0f / l_i[rr];
        float* dst = o + (size_t)(b * TT + t0 + r) * (HH * DD) + h * DD;
        float4 ov = make_float4(oa[rr][0] * invl, oa[rr][1] * invl,
                                oa[rr][2] * invl, oa[rr][3] * invl);
        *(float4*)(dst + lane * 4) = ov;
    }
}

// ---------------------------------------------------------------------------
extern "C" void kernel_launch(void* const* d_in, const int* in_sizes, int n_in,
                              void* d_out, int out_size)
{
    const float *x, *Wq, *Wk, *Wv, *Wo;
    if (in_sizes[0] == BB * TT * CC) {
        x  = (const float*)d_in[0];
        Wq = (const float*)d_in[1];
        Wk = (const float*)d_in[2];
        Wv = (const float*)d_in[3];
        Wo = (const float*)d_in[4];
    } else {
        Wk = (const float*)d_in[0];
        Wo = (const float*)d_in[1];
        Wq = (const float*)d_in[2];
        Wv = (const float*)d_in[3];
        x  = (const float*)d_in[4];
    }
    float* out = (float*)d_out;

    float *q, *k, *v, *ao;
    cudaGetSymbolAddress((void**)&q,  g_q);
    cudaGetSymbolAddress((void**)&k,  g_k);
    cudaGetSymbolAddress((void**)&v,  g_v);
    cudaGetSymbolAddress((void**)&ao, g_ao);

    init_tables_kernel<<<(TT * 64 + 255) / 256, 256>>>();

    const int gemm_smem = (2*64*PADA + 2*32*PADB) * 4;   // 53248 B (Cs unioned)
    cudaFuncSetAttribute(gemm_tf32_rope_kernel,
                         cudaFuncAttributeMaxDynamicSharedMemorySize, gemm_smem);

    dim3 blk(256);
    gemm_tf32_rope_kernel<<<dim3(HH*DD/128,  MROWS/64), blk, gemm_smem>>>(x, Wq, q, MROWS, HH*DD,  CC, 1);
    gemm_tf32_rope_kernel<<<dim3(KVH*DD/128, MROWS/64), blk, gemm_smem>>>(x, Wk, k, MROWS, KVH*DD, CC, 1);
    gemm_tf32_rope_kernel<<<dim3(KVH*DD/128, MROWS/64), blk, gemm_smem>>>(x, Wv, v, MROWS, KVH*DD, CC, 0);

    {
        const int smem_bytes = (64*128 + 64*KPITCH + 64*128 + 64*64) * 4;  // 115712
        cudaFuncSetAttribute(attn_kernel,
                             cudaFuncAttributeMaxDynamicSharedMemorySize, smem_bytes);
        attn_kernel<<<dim3(TT/64, BB*HH), 256, smem_bytes>>>(q, k, v, ao);
    }

    gemm_tf32_rope_kernel<<<dim3(CC/128, MROWS/64), blk, gemm_smem>>>(ao, Wo, out, MROWS, CC, CC, 0);
}

// round 13
// speedup vs baseline: 1.9619x; 1.9619x over previous
#include <cuda_runtime.h>
#include <math.h>
#include <cstdint>

// Problem constants
#define BB 4
#define TT 2048
#define CC 2048
#define HH 16
#define KVH 4
#define GG 4
#define DD 128
#define MROWS (BB*TT)          // 8192

#define BK 32
#define PADA 36     // A smem row pitch (words): 32 + 4
#define PADB 136    // B smem row pitch (words): 128 + 8
#define PADC 132    // C staging pitch (words)
#define KPITCH 132  // attention K smem pitch (16B-aligned; 8-lane phases conflict-free)

// ---------------- scratch (device globals; allocation is forbidden) --------
__device__ float  g_q [(size_t)MROWS * (HH*DD)];
__device__ float  g_k [(size_t)MROWS * (KVH*DD)];
__device__ float  g_v [(size_t)MROWS * (KVH*DD)];
__device__ float  g_ao[(size_t)MROWS * (HH*DD)];
__device__ float2 g_cs[TT][64];                    // cos/sin(t * 10000^(-p/64))

// ---------------------------------------------------------------------------
// Angle table: fp32-rounded angle exactly as jnp would, then double trig.
// ---------------------------------------------------------------------------
__global__ void init_tables_kernel()
{
    int idx = blockIdx.x * blockDim.x + threadIdx.x;   // t*64 + p
    if (idx >= TT * 64) return;
    int t = idx >> 6;
    int p = idx & 63;

    double ex   = (double)p / 64.0;
    float  invf = (float)pow(10000.0, -ex);
    float  ang  = (float)t * invf;
    double c, s;
    sincos((double)ang, &c, &s);
    g_cs[t][p] = make_float2((float)c, (float)s);
}

__device__ __forceinline__ float f2tf32(float x)
{
    uint32_t u;
    asm("cvt.rna.tf32.f32 %0, %1;" : "=r"(u) : "f"(x));
    return __uint_as_float(u);
}

// ---------------------------------------------------------------------------
// tf32 tensor-core GEMM with fused REVERSED-RoPE epilogue.
// R11-EXACT REVERT (validated 183us KV / ~94 TF/s): 128x128 tile, BK=32,
// 256 threads (8 warps 4x2, warp tile 32x64), 1 CTA/SM.
// ---------------------------------------------------------------------------
__global__ __launch_bounds__(256) void gemm_tf32_rope_kernel(
    const float* __restrict__ A, const float* __restrict__ B,
    float* __restrict__ C, int M, int N, int K, int rope)
{
    extern __shared__ float sm[];
    float* As = sm;                                   // 2 * 128 * PADA
    float* Bs = sm + 2 * 128 * PADA;                  // 2 * 32  * PADB
    float* Cs = sm + 2 * 128 * PADA + 2 * 32 * PADB;  // 128 * PADC

    const int tid  = threadIdx.x;
    const int lane = tid & 31;
    const int warp = tid >> 5;
    const int wm = warp >> 1;          // 0..3  (M)
    const int wn = warp & 1;           // 0..1  (N)
    const int bm = blockIdx.y * 128;
    const int bn = blockIdx.x * 128;

    const int nst = K / BK;

    float4 pa[4], pb[4];
    float acc[2][8][4];
#pragma unroll
    for (int mt = 0; mt < 2; mt++)
#pragma unroll
        for (int nt = 0; nt < 8; nt++)
#pragma unroll
            for (int c = 0; c < 4; c++) acc[mt][nt][c] = 0.f;

    // ---- prologue: stage 0 ----
    {
        const float* Ab = A + (size_t)bm * K;
        const float* Bb = B + bn;
#pragma unroll
        for (int j = 0; j < 4; j++) {
            int ia = tid + j * 256;                   // A: 128x32 -> 1024 float4
            pa[j] = *(const float4*)(Ab + (size_t)(ia >> 3) * K + (ia & 7) * 4);
            pb[j] = *(const float4*)(Bb + (size_t)(ia >> 5) * N + (ia & 31) * 4);
        }
#pragma unroll
        for (int j = 0; j < 4; j++) {
            int ia = tid + j * 256;
            float* ap = As + (ia >> 3) * PADA + (ia & 7) * 4;
            *(float4*)ap = make_float4(f2tf32(pa[j].x), f2tf32(pa[j].y),
                                       f2tf32(pa[j].z), f2tf32(pa[j].w));
            float* bp = Bs + (ia >> 5) * PADB + (ia & 31) * 4;
            *(float4*)bp = make_float4(f2tf32(pb[j].x), f2tf32(pb[j].y),
                                       f2tf32(pb[j].z), f2tf32(pb[j].w));
        }
    }
    __syncthreads();

    for (int s = 0; s < nst; s++) {
        // ---- prefetch next stage into registers ----
        if (s + 1 < nst) {
            const float* Ab = A + (size_t)bm * K + (s + 1) * BK;
            const float* Bb = B + (size_t)(s + 1) * BK * N + bn;
#pragma unroll
            for (int j = 0; j < 4; j++) {
                int ia = tid + j * 256;
                pa[j] = *(const float4*)(Ab + (size_t)(ia >> 3) * K + (ia & 7) * 4);
                pb[j] = *(const float4*)(Bb + (size_t)(ia >> 5) * N + (ia & 31) * 4);
            }
        }

        // ---- compute on current buffer ----
        {
            const float* Ab = As + (s & 1) * 128 * PADA;
            const float* Bb = Bs + (s & 1) * 32 * PADB;
#pragma unroll
            for (int kk = 0; kk < 4; kk++) {
                uint32_t af[2][4], bf[8][2];
                const int k0 = kk * 8;
                const int arow = wm * 32 + (lane >> 2);
                const int acol = k0 + (lane & 3);
#pragma unroll
                for (int mt = 0; mt < 2; mt++) {
                    const float* ap = Ab + (size_t)(arow + mt * 16) * PADA + acol;
                    af[mt][0] = __float_as_uint(ap[0]);
                    af[mt][1] = __float_as_uint(ap[8 * PADA]);
                    af[mt][2] = __float_as_uint(ap[4]);
                    af[mt][3] = __float_as_uint(ap[8 * PADA + 4]);
                }
                const int bk  = k0 + (lane & 3);
                const int bn0 = wn * 64 + (lane >> 2);
#pragma unroll
                for (int nt = 0; nt < 8; nt++) {
                    const float* bp = Bb + (size_t)bk * PADB + bn0 + nt * 8;
                    bf[nt][0] = __float_as_uint(bp[0]);
                    bf[nt][1] = __float_as_uint(bp[4 * PADB]);
                }
#pragma unroll
                for (int mt = 0; mt < 2; mt++)
#pragma unroll
                    for (int nt = 0; nt < 8; nt++)
                        asm volatile(
                            "mma.sync.aligned.m16n8k8.row.col.f32.tf32.tf32.f32 "
                            "{%0,%1,%2,%3}, {%4,%5,%6,%7}, {%8,%9}, {%0,%1,%2,%3};"
                            : "+f"(acc[mt][nt][0]), "+f"(acc[mt][nt][1]),
                              "+f"(acc[mt][nt][2]), "+f"(acc[mt][nt][3])
                            : "r"(af[mt][0]), "r"(af[mt][1]),
                              "r"(af[mt][2]), "r"(af[mt][3]),
                              "r"(bf[nt][0]), "r"(bf[nt][1]));
            }
        }

        // ---- store prefetched stage into the other buffer ----
        if (s + 1 < nst) {
            float* Ad = As + ((s + 1) & 1) * 128 * PADA;
            float* Bd = Bs + ((s + 1) & 1) * 32 * PADB;
#pragma unroll
            for (int j = 0; j < 4; j++) {
                int ia = tid + j * 256;
                float* ap = Ad + (ia >> 3) * PADA + (ia & 7) * 4;
                *(float4*)ap = make_float4(f2tf32(pa[j].x), f2tf32(pa[j].y),
                                           f2tf32(pa[j].z), f2tf32(pa[j].w));
                float* bp = Bd + (ia >> 5) * PADB + (ia & 31) * 4;
                *(float4*)bp = make_float4(f2tf32(pb[j].x), f2tf32(pb[j].y),
                                           f2tf32(pb[j].z), f2tf32(pb[j].w));
            }
        }
        __syncthreads();
    }

    // ---- epilogue: stage through smem, then (optionally) rotate and store --
#pragma unroll
    for (int mt = 0; mt < 2; mt++)
#pragma unroll
        for (int nt = 0; nt < 8; nt++) {
            int r0 = wm * 32 + mt * 16 + (lane >> 2);
            int c0 = wn * 64 + nt * 8 + (lane & 3) * 2;
            *(float2*)&Cs[r0 * PADC + c0]       = make_float2(acc[mt][nt][0], acc[mt][nt][1]);
            *(float2*)&Cs[(r0 + 8) * PADC + c0] = make_float2(acc[mt][nt][2], acc[mt][nt][3]);
        }
    __syncthreads();

    if (rope) {
#pragma unroll
        for (int j = 0; j < 32; j++) {
            int idx = tid + j * 256;       // 128 rows * 64 pairs
            int row = idx >> 6, p = idx & 63;
            int t = (bm + row) & (TT - 1);
            float2 cs = g_cs[t][p];
            float a0 = Cs[row * PADC + p];
            float a1 = Cs[row * PADC + p + 64];
            float* crow = C + (size_t)(bm + row) * N + bn;
            crow[p]      = a0 * cs.x + a1 * cs.y;   // reversed rotation
            crow[p + 64] = a1 * cs.x - a0 * cs.y;
        }
    } else {
#pragma unroll
        for (int j = 0; j < 16; j++) {
            int idx = tid + j * 256;       // 128 rows * 32 float4
            int row = idx >> 5, c4 = idx & 31;
            *(float4*)(C + (size_t)(bm + row) * N + bn + c4 * 4) =
                *(float4*)&Cs[row * PADC + c4 * 4];
        }
    }
}

// ---------------------------------------------------------------------------
// Attention (causal, GQA), warp-private, LOOP-REORDERED for smem reuse:
//  - QK: K float4 loaded once per d-chunk, reused across all 8 rows
//        (Q reads are warp-broadcasts). Accumulation order per row unchanged.
//  - PV: V float4 loaded once per 4-col chunk, reused across 8 rows;
//        P read as broadcast float4. Accumulation order per row unchanged.
// smem: Q[64][128] | K[64][KPITCH] | V[64][128] | P[64][64]
// ---------------------------------------------------------------------------
__global__ __launch_bounds__(256) void attn_kernel(
    const float* __restrict__ q, const float* __restrict__ k,
    const float* __restrict__ v, float* __restrict__ o)
{
    extern __shared__ float smem[];
    float* sQ = smem;                       // 8192
    float* sK = sQ + 64 * 128;              // 64*KPITCH = 8448
    float* sV = sK + 64 * KPITCH;           // 8192
    float* sP = sV + 64 * 128;              // 4096

    const int qi = blockIdx.x;
    const int bh = blockIdx.y;
    const int b  = bh / HH;
    const int h  = bh % HH;
    const int kvh = h / GG;
    const int t0 = qi * 64;

    const int tid  = threadIdx.x;
    const int warp = tid >> 5;
    const int lane = tid & 31;

    const float scale = 0.08838834764831845f;

    // ---- load Q tile (pre-scaled), vectorized
#pragma unroll
    for (int j = 0; j < 8; j++) {
        int idx4 = tid + j * 256;           // 2048 float4
        int r = idx4 >> 5, c4 = idx4 & 31;
        float4 qv = *(const float4*)(q + (size_t)(b * TT + t0 + r) * (HH * DD) + h * DD + c4 * 4);
        qv.x *= scale; qv.y *= scale; qv.z *= scale; qv.w *= scale;
        *(float4*)&sQ[r * 128 + c4 * 4] = qv;
    }

    float m_i[8], l_i[8], oa[8][4];
#pragma unroll
    for (int rr = 0; rr < 8; rr++) {
        m_i[rr] = -1e30f; l_i[rr] = 0.f;
#pragma unroll
        for (int j = 0; j < 4; j++) oa[rr][j] = 0.f;
    }

    for (int jt = 0; jt <= qi; jt++) {
        __syncthreads();

        // ---- load K/V tiles, vectorized coalesced
#pragma unroll
        for (int j = 0; j < 8; j++) {
            int idx4 = tid + j * 256;
            int r = idx4 >> 5, c4 = idx4 & 31;
            size_t gofs = (size_t)(b * TT + jt * 64 + r) * (KVH * DD) + kvh * DD + c4 * 4;
            *(float4*)&sK[r * KPITCH + c4 * 4] = *(const float4*)(k + gofs);
            *(float4*)&sV[r * 128    + c4 * 4] = *(const float4*)(v + gofs);
        }
        __syncthreads();

        // ---- QK: K reused across 8 rows; d ascending (order-preserving)
        float s0[8], s1[8];
#pragma unroll
        for (int rr = 0; rr < 8; rr++) { s0[rr] = 0.f; s1[rr] = 0.f; }

        const float* k0p = &sK[lane * KPITCH];
        const float* k1p = &sK[(lane + 32) * KPITCH];
        const float* qbase = &sQ[warp * 8 * 128];
#pragma unroll
        for (int d = 0; d < 128; d += 4) {
            float4 k0 = *(const float4*)(k0p + d);
            float4 k1 = *(const float4*)(k1p + d);
#pragma unroll
            for (int rr = 0; rr < 8; rr++) {
                float4 qv = *(const float4*)(qbase + rr * 128 + d);   // broadcast
                s0[rr] += qv.x * k0.x + qv.y * k0.y + qv.z * k0.z + qv.w * k0.w;
                s1[rr] += qv.x * k1.x + qv.y * k1.y + qv.z * k1.z + qv.w * k1.w;
            }
        }

        // ---- softmax per row (unchanged semantics)
#pragma unroll
        for (int rr = 0; rr < 8; rr++) {
            int r = warp * 8 + rr;
            int qglob = t0 + r;
            float v0 = s0[rr], v1 = s1[rr];
            if (jt * 64 + lane      > qglob) v0 = -1e30f;
            if (jt * 64 + lane + 32 > qglob) v1 = -1e30f;

            float mx = fmaxf(v0, v1);
#pragma unroll
            for (int off = 16; off >= 1; off >>= 1)
                mx = fmaxf(mx, __shfl_xor_sync(0xffffffffu, mx, off));

            float m_new = fmaxf(m_i[rr], mx);
            float p0 = __expf(v0 - m_new);
            float p1 = __expf(v1 - m_new);
            float rs = p0 + p1;
#pragma unroll
            for (int off = 16; off >= 1; off >>= 1)
                rs += __shfl_xor_sync(0xffffffffu, rs, off);

            float f = __expf(m_i[rr] - m_new);
            l_i[rr] = l_i[rr] * f + rs;
            m_i[rr] = m_new;
#pragma unroll
            for (int j = 0; j < 4; j++) oa[rr][j] *= f;

            sP[r * 64 + lane]      = p0;
            sP[r * 64 + lane + 32] = p1;
        }
        __syncwarp();   // warp-private sP strip visible to all lanes

        // ---- PV: V reused across 8 rows; c ascending (order-preserving)
        const float* pbase = &sP[warp * 8 * 64];
#pragma unroll
        for (int c0 = 0; c0 < 64; c0 += 4) {
            float4 vv0 = *(const float4*)&sV[(c0 + 0) * 128 + lane * 4];
            float4 vv1 = *(const float4*)&sV[(c0 + 1) * 128 + lane * 4];
            float4 vv2 = *(const float4*)&sV[(c0 + 2) * 128 + lane * 4];
            float4 vv3 = *(const float4*)&sV[(c0 + 3) * 128 + lane * 4];
#pragma unroll
            for (int rr = 0; rr < 8; rr++) {
                float4 pv = *(const float4*)(pbase + rr * 64 + c0);   // broadcast
                oa[rr][0] += pv.x * vv0.x + pv.y * vv1.x + pv.z * vv2.x + pv.w * vv3.x;
                oa[rr][1] += pv.x * vv0.y + pv.y * vv1.y + pv.z * vv2.y + pv.w * vv3.y;
                oa[rr][2] += pv.x * vv0.z + pv.y * vv1.z + pv.z * vv2.z + pv.w * vv3.z;
                oa[rr][3] += pv.x * vv0.w + pv.y * vv1.w + pv.z * vv2.w + pv.w * vv3.w;
            }
        }
    }

    // ---- epilogue: normalize and store
#pragma unroll
    for (int rr = 0; rr < 8; rr++) {
        int r = warp * 8 + rr;
        float invl = 1.0f / l_i[rr];
        float* dst = o + (size_t)(b * TT + t0 + r) * (HH * DD) + h * DD;
        float4 ov = make_float4(oa[rr][0] * invl, oa[rr][1] * invl,
                                oa[rr][2] * invl, oa[rr][3] * invl);
        *(float4*)(dst + lane * 4) = ov;
    }
}

// ---------------------------------------------------------------------------
extern "C" void kernel_launch(void* const* d_in, const int* in_sizes, int n_in,
                              void* d_out, int out_size)
{
    const float *x, *Wq, *Wk, *Wv, *Wo;
    if (in_sizes[0] == BB * TT * CC) {
        x  = (const float*)d_in[0];
        Wq = (const float*)d_in[1];
        Wk = (const float*)d_in[2];
        Wv = (const float*)d_in[3];
        Wo = (const float*)d_in[4];
    } else {
        Wk = (const float*)d_in[0];
        Wo = (const float*)d_in[1];
        Wq = (const float*)d_in[2];
        Wv = (const float*)d_in[3];
        x  = (const float*)d_in[4];
    }
    float* out = (float*)d_out;

    float *q, *k, *v, *ao;
    cudaGetSymbolAddress((void**)&q,  g_q);
    cudaGetSymbolAddress((void**)&k,  g_k);
    cudaGetSymbolAddress((void**)&v,  g_v);
    cudaGetSymbolAddress((void**)&ao, g_ao);

    init_tables_kernel<<<(TT * 64 + 255) / 256, 256>>>();

    const int gemm_smem = (2*128*PADA + 2*32*PADB + 128*PADC) * 4;  // 139264 B
    cudaFuncSetAttribute(gemm_tf32_rope_kernel,
                         cudaFuncAttributeMaxDynamicSharedMemorySize, gemm_smem);

    dim3 blk(256);
    gemm_tf32_rope_kernel<<<dim3(HH*DD/128,  MROWS/128), blk, gemm_smem>>>(x, Wq, q, MROWS, HH*DD,  CC, 1);
    gemm_tf32_rope_kernel<<<dim3(KVH*DD/128, MROWS/128), blk, gemm_smem>>>(x, Wk, k, MROWS, KVH*DD, CC, 1);
    gemm_tf32_rope_kernel<<<dim3(KVH*DD/128, MROWS/128), blk, gemm_smem>>>(x, Wv, v, MROWS, KVH*DD, CC, 0);

    {
        const int smem_bytes = (64*128 + 64*KPITCH + 64*128 + 64*64) * 4;  // 115712
        cudaFuncSetAttribute(attn_kernel,
                             cudaFuncAttributeMaxDynamicSharedMemorySize, smem_bytes);
        attn_kernel<<<dim3(TT/64, BB*HH), 256, smem_bytes>>>(q, k, v, ao);
    }

    gemm_tf32_rope_kernel<<<dim3(CC/128, MROWS/128), blk, gemm_smem>>>(ao, Wo, out, MROWS, CC, CC, 0);
}

// round 14
// speedup vs baseline: 3.3319x; 1.6983x over previous
#include <cuda_runtime.h>
#include <math.h>
#include <cstdint>

// Problem constants
#define BB 4
#define TT 2048
#define CC 2048
#define HH 16
#define KVH 4
#define GG 4
#define DD 128
#define MROWS (BB*TT)          // 8192

#define BK 32
#define PADA 36     // GEMM A smem row pitch (words)
#define PADB 136    // GEMM B smem row pitch (words)
#define PADC 132    // GEMM C staging pitch (words)

#define QP 132      // attn Q pitch  (132 mod 32 = 4 -> conflict-free frags)
#define KVP 132     // attn K/V pitch
#define PP 68       // attn P pitch  (68 mod 32 = 4)

// ---------------- scratch (device globals; allocation is forbidden) --------
__device__ float  g_q [(size_t)MROWS * (HH*DD)];
__device__ float  g_k [(size_t)MROWS * (KVH*DD)];
__device__ float  g_v [(size_t)MROWS * (KVH*DD)];
__device__ float  g_ao[(size_t)MROWS * (HH*DD)];
__device__ float2 g_cs[TT][64];                    // cos/sin(t * 10000^(-p/64))

// ---------------------------------------------------------------------------
// Angle table: fp32-rounded angle exactly as jnp would, then double trig.
// ---------------------------------------------------------------------------
__global__ void init_tables_kernel()
{
    int idx = blockIdx.x * blockDim.x + threadIdx.x;   // t*64 + p
    if (idx >= TT * 64) return;
    int t = idx >> 6;
    int p = idx & 63;

    double ex   = (double)p / 64.0;
    float  invf = (float)pow(10000.0, -ex);
    float  ang  = (float)t * invf;
    double c, s;
    sincos((double)ang, &c, &s);
    g_cs[t][p] = make_float2((float)c, (float)s);
}

__device__ __forceinline__ float f2tf32(float x)
{
    uint32_t u;
    asm("cvt.rna.tf32.f32 %0, %1;" : "=r"(u) : "f"(x));
    return __uint_as_float(u);
}

#define MMA_TF32(ACC, A0, A1, A2, A3, B0, B1)                                  \
    asm volatile(                                                              \
        "mma.sync.aligned.m16n8k8.row.col.f32.tf32.tf32.f32 "                  \
        "{%0,%1,%2,%3}, {%4,%5,%6,%7}, {%8,%9}, {%0,%1,%2,%3};"                \
        : "+f"((ACC)[0]), "+f"((ACC)[1]), "+f"((ACC)[2]), "+f"((ACC)[3])       \
        : "r"(A0), "r"(A1), "r"(A2), "r"(A3), "r"(B0), "r"(B1))

// ---------------------------------------------------------------------------
// tf32 tensor-core GEMM with fused REVERSED-RoPE epilogue. R13-EXACT
// (validated 180.6us KV): 128x128 tile, BK=32, 8 warps 4x2, 1 CTA/SM.
// ---------------------------------------------------------------------------
__global__ __launch_bounds__(256) void gemm_tf32_rope_kernel(
    const float* __restrict__ A, const float* __restrict__ B,
    float* __restrict__ C, int M, int N, int K, int rope)
{
    extern __shared__ float sm[];
    float* As = sm;                                   // 2 * 128 * PADA
    float* Bs = sm + 2 * 128 * PADA;                  // 2 * 32  * PADB
    float* Cs = sm + 2 * 128 * PADA + 2 * 32 * PADB;  // 128 * PADC

    const int tid  = threadIdx.x;
    const int lane = tid & 31;
    const int warp = tid >> 5;
    const int wm = warp >> 1;
    const int wn = warp & 1;
    const int bm = blockIdx.y * 128;
    const int bn = blockIdx.x * 128;

    const int nst = K / BK;

    float4 pa[4], pb[4];
    float acc[2][8][4];
#pragma unroll
    for (int mt = 0; mt < 2; mt++)
#pragma unroll
        for (int nt = 0; nt < 8; nt++)
#pragma unroll
            for (int c = 0; c < 4; c++) acc[mt][nt][c] = 0.f;

    {
        const float* Ab = A + (size_t)bm * K;
        const float* Bb = B + bn;
#pragma unroll
        for (int j = 0; j < 4; j++) {
            int ia = tid + j * 256;
            pa[j] = *(const float4*)(Ab + (size_t)(ia >> 3) * K + (ia & 7) * 4);
            pb[j] = *(const float4*)(Bb + (size_t)(ia >> 5) * N + (ia & 31) * 4);
        }
#pragma unroll
        for (int j = 0; j < 4; j++) {
            int ia = tid + j * 256;
            float* ap = As + (ia >> 3) * PADA + (ia & 7) * 4;
            *(float4*)ap = make_float4(f2tf32(pa[j].x), f2tf32(pa[j].y),
                                       f2tf32(pa[j].z), f2tf32(pa[j].w));
            float* bp = Bs + (ia >> 5) * PADB + (ia & 31) * 4;
            *(float4*)bp = make_float4(f2tf32(pb[j].x), f2tf32(pb[j].y),
                                       f2tf32(pb[j].z), f2tf32(pb[j].w));
        }
    }
    __syncthreads();

    for (int s = 0; s < nst; s++) {
        if (s + 1 < nst) {
            const float* Ab = A + (size_t)bm * K + (s + 1) * BK;
            const float* Bb = B + (size_t)(s + 1) * BK * N + bn;
#pragma unroll
            for (int j = 0; j < 4; j++) {
                int ia = tid + j * 256;
                pa[j] = *(const float4*)(Ab + (size_t)(ia >> 3) * K + (ia & 7) * 4);
                pb[j] = *(const float4*)(Bb + (size_t)(ia >> 5) * N + (ia & 31) * 4);
            }
        }

        {
            const float* Ab = As + (s & 1) * 128 * PADA;
            const float* Bb = Bs + (s & 1) * 32 * PADB;
#pragma unroll
            for (int kk = 0; kk < 4; kk++) {
                uint32_t af[2][4], bf[8][2];
                const int k0 = kk * 8;
                const int arow = wm * 32 + (lane >> 2);
                const int acol = k0 + (lane & 3);
#pragma unroll
                for (int mt = 0; mt < 2; mt++) {
                    const float* ap = Ab + (size_t)(arow + mt * 16) * PADA + acol;
                    af[mt][0] = __float_as_uint(ap[0]);
                    af[mt][1] = __float_as_uint(ap[8 * PADA]);
                    af[mt][2] = __float_as_uint(ap[4]);
                    af[mt][3] = __float_as_uint(ap[8 * PADA + 4]);
                }
                const int bk  = k0 + (lane & 3);
                const int bn0 = wn * 64 + (lane >> 2);
#pragma unroll
                for (int nt = 0; nt < 8; nt++) {
                    const float* bp = Bb + (size_t)bk * PADB + bn0 + nt * 8;
                    bf[nt][0] = __float_as_uint(bp[0]);
                    bf[nt][1] = __float_as_uint(bp[4 * PADB]);
                }
#pragma unroll
                for (int mt = 0; mt < 2; mt++)
#pragma unroll
                    for (int nt = 0; nt < 8; nt++)
                        MMA_TF32(acc[mt][nt], af[mt][0], af[mt][1], af[mt][2], af[mt][3],
                                 bf[nt][0], bf[nt][1]);
            }
        }

        if (s + 1 < nst) {
            float* Ad = As + ((s + 1) & 1) * 128 * PADA;
            float* Bd = Bs + ((s + 1) & 1) * 32 * PADB;
#pragma unroll
            for (int j = 0; j < 4; j++) {
                int ia = tid + j * 256;
                float* ap = Ad + (ia >> 3) * PADA + (ia & 7) * 4;
                *(float4*)ap = make_float4(f2tf32(pa[j].x), f2tf32(pa[j].y),
                                           f2tf32(pa[j].z), f2tf32(pa[j].w));
                float* bp = Bd + (ia >> 5) * PADB + (ia & 31) * 4;
                *(float4*)bp = make_float4(f2tf32(pb[j].x), f2tf32(pb[j].y),
                                           f2tf32(pb[j].z), f2tf32(pb[j].w));
            }
        }
        __syncthreads();
    }

#pragma unroll
    for (int mt = 0; mt < 2; mt++)
#pragma unroll
        for (int nt = 0; nt < 8; nt++) {
            int r0 = wm * 32 + mt * 16 + (lane >> 2);
            int c0 = wn * 64 + nt * 8 + (lane & 3) * 2;
            *(float2*)&Cs[r0 * PADC + c0]       = make_float2(acc[mt][nt][0], acc[mt][nt][1]);
            *(float2*)&Cs[(r0 + 8) * PADC + c0] = make_float2(acc[mt][nt][2], acc[mt][nt][3]);
        }
    __syncthreads();

    if (rope) {
#pragma unroll
        for (int j = 0; j < 32; j++) {
            int idx = tid + j * 256;
            int row = idx >> 6, p = idx & 63;
            int t = (bm + row) & (TT - 1);
            float2 cs = g_cs[t][p];
            float a0 = Cs[row * PADC + p];
            float a1 = Cs[row * PADC + p + 64];
            float* crow = C + (size_t)(bm + row) * N + bn;
            crow[p]      = a0 * cs.x + a1 * cs.y;   // reversed rotation (R9)
            crow[p + 64] = a1 * cs.x - a0 * cs.y;
        }
    } else {
#pragma unroll
        for (int j = 0; j < 16; j++) {
            int idx = tid + j * 256;
            int row = idx >> 5, c4 = idx & 31;
            *(float4*)(C + (size_t)(bm + row) * N + bn + c4 * 4) =
                *(float4*)&Cs[row * PADC + c4 * 4];
        }
    }
}

// ---------------------------------------------------------------------------
// Attention (causal, GQA) on tf32 tensor cores.
// Block = 128 query rows, 8 warps; warp = 16 rows x full 64-key tile.
// QK: S(16x64) via m16n8k8; softmax warp-local on C-fragments (rows live in
// lane-quads, reductions = shfl_xor 1,2); P staged tf32 in warp-private smem;
// PV: O(16x128) via m16n8k8 from P(A) x V(B).
// smem: Q[128][QP] tf32 | K[64][KVP] tf32 | V[64][KVP] tf32 | P[128][PP] tf32
// ---------------------------------------------------------------------------
__global__ __launch_bounds__(256) void attn_mma_kernel(
    const float* __restrict__ q, const float* __restrict__ k,
    const float* __restrict__ v, float* __restrict__ o)
{
    extern __shared__ float smem[];
    float* sQ = smem;                        // 128*QP
    float* sK = sQ + 128 * QP;               // 64*KVP
    float* sV = sK + 64 * KVP;               // 64*KVP
    float* sP = sV + 64 * KVP;               // 128*PP

    const int qi = blockIdx.x;               // 128-row tile
    const int bh = blockIdx.y;
    const int b  = bh / HH;
    const int h  = bh % HH;
    const int kvh = h / GG;
    const int t0 = qi * 128;

    const int tid  = threadIdx.x;
    const int warp = tid >> 5;
    const int lane = tid & 31;
    const int lq   = lane >> 2;              // 0..7 (fragment row)
    const int lr   = lane & 3;               // 0..3 (fragment col pair)

    const float scale = 0.08838834764831845f;

    // ---- load Q tile (scaled, tf32) : 128x128 = 4096 float4
#pragma unroll
    for (int j = 0; j < 16; j++) {
        int idx4 = tid + j * 256;
        int r = idx4 >> 5, c4 = idx4 & 31;
        float4 qv = *(const float4*)(q + (size_t)(b * TT + t0 + r) * (HH * DD) + h * DD + c4 * 4);
        *(float4*)&sQ[r * QP + c4 * 4] =
            make_float4(f2tf32(qv.x * scale), f2tf32(qv.y * scale),
                        f2tf32(qv.z * scale), f2tf32(qv.w * scale));
    }

    // per-thread softmax state for rows r0 = warp*16+lq, r1 = r0+8
    float m0 = -1e30f, m1 = -1e30f, l0 = 0.f, l1 = 0.f;
    float O[16][4];
#pragma unroll
    for (int nt = 0; nt < 16; nt++)
#pragma unroll
        for (int c = 0; c < 4; c++) O[nt][c] = 0.f;

    const int row0 = warp * 16 + lq;         // block-relative fragment rows
    const int nkt  = qi * 2 + 2;             // key tiles (last partially masked)

    for (int jt = 0; jt < nkt; jt++) {
        __syncthreads();
        // ---- load K/V tile (tf32): 64x128 = 2048 float4 each
#pragma unroll
        for (int j = 0; j < 8; j++) {
            int idx4 = tid + j * 256;
            int r = idx4 >> 5, c4 = idx4 & 31;
            size_t gofs = (size_t)(b * TT + jt * 64 + r) * (KVH * DD) + kvh * DD + c4 * 4;
            float4 kv = *(const float4*)(k + gofs);
            float4 vv = *(const float4*)(v + gofs);
            *(float4*)&sK[r * KVP + c4 * 4] =
                make_float4(f2tf32(kv.x), f2tf32(kv.y), f2tf32(kv.z), f2tf32(kv.w));
            *(float4*)&sV[r * KVP + c4 * 4] =
                make_float4(f2tf32(vv.x), f2tf32(vv.y), f2tf32(vv.z), f2tf32(vv.w));
        }
        __syncthreads();

        // ---- QK: S[16][64] ----
        float sacc[8][4];
#pragma unroll
        for (int nt = 0; nt < 8; nt++)
#pragma unroll
            for (int c = 0; c < 4; c++) sacc[nt][c] = 0.f;

#pragma unroll
        for (int ks = 0; ks < 16; ks++) {
            const int k0 = ks * 8;
            const float* ap = sQ + (size_t)row0 * QP + k0 + lr;
            uint32_t a0 = __float_as_uint(ap[0]);
            uint32_t a1 = __float_as_uint(ap[8 * QP]);
            uint32_t a2 = __float_as_uint(ap[4]);
            uint32_t a3 = __float_as_uint(ap[8 * QP + 4]);
#pragma unroll
            for (int nt = 0; nt < 8; nt++) {
                const float* bp = sK + (size_t)(nt * 8 + lq) * KVP + k0 + lr;
                uint32_t b0 = __float_as_uint(bp[0]);
                uint32_t b1 = __float_as_uint(bp[4]);
                MMA_TF32(sacc[nt], a0, a1, a2, a3, b0, b1);
            }
        }

        // ---- causal mask (global indices) ----
        const int kbase = jt * 64;
        if (kbase + 63 > t0 + warp * 16) {
            int rg0 = t0 + row0, rg1 = rg0 + 8;
#pragma unroll
            for (int nt = 0; nt < 8; nt++) {
                int cg = kbase + nt * 8 + 2 * lr;
                if (cg     > rg0) sacc[nt][0] = -1e30f;
                if (cg + 1 > rg0) sacc[nt][1] = -1e30f;
                if (cg     > rg1) sacc[nt][2] = -1e30f;
                if (cg + 1 > rg1) sacc[nt][3] = -1e30f;
            }
        }

        // ---- warp-local online softmax ----
        float mx0 = -1e30f, mx1 = -1e30f;
#pragma unroll
        for (int nt = 0; nt < 8; nt++) {
            mx0 = fmaxf(mx0, fmaxf(sacc[nt][0], sacc[nt][1]));
            mx1 = fmaxf(mx1, fmaxf(sacc[nt][2], sacc[nt][3]));
        }
        mx0 = fmaxf(mx0, __shfl_xor_sync(0xffffffffu, mx0, 1));
        mx0 = fmaxf(mx0, __shfl_xor_sync(0xffffffffu, mx0, 2));
        mx1 = fmaxf(mx1, __shfl_xor_sync(0xffffffffu, mx1, 1));
        mx1 = fmaxf(mx1, __shfl_xor_sync(0xffffffffu, mx1, 2));

        float mn0 = fmaxf(m0, mx0), mn1 = fmaxf(m1, mx1);
        float f0 = __expf(m0 - mn0), f1 = __expf(m1 - mn1);

        float rs0 = 0.f, rs1 = 0.f;
#pragma unroll
        for (int nt = 0; nt < 8; nt++) {
            float p0 = __expf(sacc[nt][0] - mn0);
            float p1 = __expf(sacc[nt][1] - mn0);
            float p2 = __expf(sacc[nt][2] - mn1);
            float p3 = __expf(sacc[nt][3] - mn1);
            rs0 += p0 + p1; rs1 += p2 + p3;
            // stage P (tf32) into warp-private strip
            float* pp = sP + (size_t)row0 * PP + nt * 8 + 2 * lr;
            *(float2*)pp            = make_float2(f2tf32(p0), f2tf32(p1));
            *(float2*)(pp + 8 * PP) = make_float2(f2tf32(p2), f2tf32(p3));
        }
        rs0 += __shfl_xor_sync(0xffffffffu, rs0, 1);
        rs0 += __shfl_xor_sync(0xffffffffu, rs0, 2);
        rs1 += __shfl_xor_sync(0xffffffffu, rs1, 1);
        rs1 += __shfl_xor_sync(0xffffffffu, rs1, 2);

        l0 = l0 * f0 + rs0;  m0 = mn0;
        l1 = l1 * f1 + rs1;  m1 = mn1;

#pragma unroll
        for (int nt = 0; nt < 16; nt++) {
            O[nt][0] *= f0; O[nt][1] *= f0;
            O[nt][2] *= f1; O[nt][3] *= f1;
        }
        __syncwarp();

        // ---- PV: O += P(16x64) x V(64x128) ----
#pragma unroll
        for (int ks = 0; ks < 8; ks++) {
            const int k0 = ks * 8;
            const float* ap = sP + (size_t)row0 * PP + k0 + lr;
            uint32_t a0 = __float_as_uint(ap[0]);
            uint32_t a1 = __float_as_uint(ap[8 * PP]);
            uint32_t a2 = __float_as_uint(ap[4]);
            uint32_t a3 = __float_as_uint(ap[8 * PP + 4]);
#pragma unroll
            for (int nt = 0; nt < 16; nt++) {
                const float* bp = sV + (size_t)(k0 + lr) * KVP + nt * 8 + lq;
                uint32_t b0 = __float_as_uint(bp[0]);
                uint32_t b1 = __float_as_uint(bp[4 * KVP]);
                MMA_TF32(O[nt], a0, a1, a2, a3, b0, b1);
            }
        }
    }

    // ---- epilogue: normalize, store ----
    float il0 = 1.0f / l0, il1 = 1.0f / l1;
    float* d0 = o + (size_t)(b * TT + t0 + row0) * (HH * DD) + h * DD;
    float* d1 = d0 + 8 * (HH * DD);
#pragma unroll
    for (int nt = 0; nt < 16; nt++) {
        int c0 = nt * 8 + 2 * lr;
        *(float2*)(d0 + c0) = make_float2(O[nt][0] * il0, O[nt][1] * il0);
        *(float2*)(d1 + c0) = make_float2(O[nt][2] * il1, O[nt][3] * il1);
    }
}

// ---------------------------------------------------------------------------
extern "C" void kernel_launch(void* const* d_in, const int* in_sizes, int n_in,
                              void* d_out, int out_size)
{
    const float *x, *Wq, *Wk, *Wv, *Wo;
    if (in_sizes[0] == BB * TT * CC) {
        x  = (const float*)d_in[0];
        Wq = (const float*)d_in[1];
        Wk = (const float*)d_in[2];
        Wv = (const float*)d_in[3];
        Wo = (const float*)d_in[4];
    } else {
        Wk = (const float*)d_in[0];
        Wo = (const float*)d_in[1];
        Wq = (const float*)d_in[2];
        Wv = (const float*)d_in[3];
        x  = (const float*)d_in[4];
    }
    float* out = (float*)d_out;

    float *q, *k, *v, *ao;
    cudaGetSymbolAddress((void**)&q,  g_q);
    cudaGetSymbolAddress((void**)&k,  g_k);
    cudaGetSymbolAddress((void**)&v,  g_v);
    cudaGetSymbolAddress((void**)&ao, g_ao);

    init_tables_kernel<<<(TT * 64 + 255) / 256, 256>>>();

    const int gemm_smem = (2*128*PADA + 2*32*PADB + 128*PADC) * 4;  // 139264 B
    cudaFuncSetAttribute(gemm_tf32_rope_kernel,
                         cudaFuncAttributeMaxDynamicSharedMemorySize, gemm_smem);

    dim3 blk(256);
    gemm_tf32_rope_kernel<<<dim3(HH*DD/128,  MROWS/128), blk, gemm_smem>>>(x, Wq, q, MROWS, HH*DD,  CC, 1);
    gemm_tf32_rope_kernel<<<dim3(KVH*DD/128, MROWS/128), blk, gemm_smem>>>(x, Wk, k, MROWS, KVH*DD, CC, 1);
    gemm_tf32_rope_kernel<<<dim3(KVH*DD/128, MROWS/128), blk, gemm_smem>>>(x, Wv, v, MROWS, KVH*DD, CC, 0);

    {
        const int attn_smem = (128*QP + 64*KVP + 64*KVP + 128*PP) * 4;  // 169984 B
        cudaFuncSetAttribute(attn_mma_kernel,
                             cudaFuncAttributeMaxDynamicSharedMemorySize, attn_smem);
        attn_mma_kernel<<<dim3(TT/128, BB*HH), 256, attn_smem>>>(q, k, v, ao);
    }

    gemm_tf32_rope_kernel<<<dim3(CC/128, MROWS/128), blk, gemm_smem>>>(ao, Wo, out, MROWS, CC, CC, 0);
}

// round 16
// speedup vs baseline: 3.4327x; 1.0303x over previous
#include <cuda_runtime.h>
#include <math.h>
#include <cstdint>

// Problem constants
#define BB 4
#define TT 2048
#define CC 2048
#define HH 16
#define KVH 4
#define GG 4
#define DD 128
#define MROWS (BB*TT)          // 8192

#define BK 32
#define PADC 132               // C staging pitch (words)

// packed-fragment layout constants
#define APITCH 132             // per-(f,kk) block pitch (floats)
#define BPITCH 66              // per-(kk,nf) block pitch (floats)
#define ASTG   (32 * APITCH)   // 4224 floats per stage (8 f-frags * 4 kk)
#define BSTG   (64 * BPITCH)   // 4224 floats per stage (4 kk * 16 nf)

#define QP 132      // attn Q pitch
#define KVP 132     // attn K/V pitch
#define PP 68       // attn P pitch

// ---------------- scratch (device globals; allocation is forbidden) --------
__device__ float  g_q [(size_t)MROWS * (HH*DD)];
__device__ float  g_k [(size_t)MROWS * (KVH*DD)];
__device__ float  g_v [(size_t)MROWS * (KVH*DD)];
__device__ float  g_ao[(size_t)MROWS * (HH*DD)];
__device__ float2 g_cs[TT][64];                    // cos/sin(t * 10000^(-p/64))

// ---------------------------------------------------------------------------
// Angle table: fp32-rounded angle exactly as jnp would, then double trig.
// ---------------------------------------------------------------------------
__global__ void init_tables_kernel()
{
    int idx = blockIdx.x * blockDim.x + threadIdx.x;   // t*64 + p
    if (idx >= TT * 64) return;
    int t = idx >> 6;
    int p = idx & 63;

    double ex   = (double)p / 64.0;
    float  invf = (float)pow(10000.0, -ex);
    float  ang  = (float)t * invf;
    double c, s;
    sincos((double)ang, &c, &s);
    g_cs[t][p] = make_float2((float)c, (float)s);
}

__device__ __forceinline__ float f2tf32(float x)
{
    uint32_t u;
    asm("cvt.rna.tf32.f32 %0, %1;" : "=r"(u) : "f"(x));
    return __uint_as_float(u);
}

#define MMA_TF32(ACC, A0, A1, A2, A3, B0, B1)                                  \
    asm volatile(                                                              \
        "mma.sync.aligned.m16n8k8.row.col.f32.tf32.tf32.f32 "                  \
        "{%0,%1,%2,%3}, {%4,%5,%6,%7}, {%8,%9}, {%0,%1,%2,%3};"                \
        : "+f"((ACC)[0]), "+f"((ACC)[1]), "+f"((ACC)[2]), "+f"((ACC)[3])       \
        : "r"(A0), "r"(A1), "r"(A2), "r"(A3), "r"(B0), "r"(B1))

// ---------------------------------------------------------------------------
// tf32 tensor-core GEMM, fragment-packed smem, fused REVERSED-RoPE epilogue.
// 128x128 tile, BK=32, 256 threads (8 warps 4x2, warp tile 32x64), 1 CTA/SM.
//
// Packed layouts (written on the tf32-convert store path, per stage):
//   A_pk[(f*4 + kk)*APITCH + (lq*4+lr)*4 + e],  e = half + 2*kc
//     -> warp fragment (f, kk) for lane (lq,lr) is ONE float4 at +lane*4.
//   B_pk[(kk*16 + nf)*BPITCH + (lq*4+lr)*2 + kc]
//     -> warp fragment (kk, nf) for lane is ONE float2 at +lane*2.
// Arithmetic and accumulation order identical to R14 (rel_err canary).
// ---------------------------------------------------------------------------
__global__ __launch_bounds__(256) void gemm_tf32_rope_kernel(
    const float* __restrict__ A, const float* __restrict__ B,
    float* __restrict__ C, int M, int N, int K, int rope)
{
    extern __shared__ float sm[];
    float* As = sm;                    // 2 * ASTG
    float* Bs = sm + 2 * ASTG;         // 2 * BSTG
    float* Cs = sm;                    // epilogue overlay (mainloop drained)

    const int tid  = threadIdx.x;
    const int lane = tid & 31;
    const int warp = tid >> 5;
    const int wm = warp >> 1;          // 0..3  (M)
    const int wn = warp & 1;           // 0..1  (N)
    const int bm = blockIdx.y * 128;
    const int bn = blockIdx.x * 128;

    const int nst = K / BK;

    float4 pa[4], pb[4];
    float acc[2][8][4];
#pragma unroll
    for (int mt = 0; mt < 2; mt++)
#pragma unroll
        for (int nt = 0; nt < 8; nt++)
#pragma unroll
            for (int c = 0; c < 4; c++) acc[mt][nt][c] = 0.f;

    // ---- packed store helpers (indices derived from flat id) ----
    //  A: ia in [0,1024): r=ia>>3 (row), c8=ia&7 (float4 slot): cols c8*4..+3
    //  B: ib in [0,1024): k=ib>>5, n0=(ib&31)*4
#define STORE_A_PK(buf, ia, v) do {                                            \
        int _r = (ia) >> 3, _c8 = (ia) & 7;                                    \
        float* _p = (buf) + (((_r >> 4) * 4 + (_c8 >> 1)) * APITCH)            \
                  + ((_r & 7) * 16) + (((_r >> 3) & 1) + 2 * (_c8 & 1));       \
        _p[0]  = f2tf32((v).x);  _p[4]  = f2tf32((v).y);                       \
        _p[8]  = f2tf32((v).z);  _p[12] = f2tf32((v).w);                       \
    } while (0)
#define STORE_B_PK(buf, ib, v) do {                                            \
        int _k = (ib) >> 5, _n0 = ((ib) & 31) * 4;                             \
        float* _p = (buf) + (((_k >> 3) * 16 + (_n0 >> 3)) * BPITCH)           \
                  + ((_n0 & 7) * 8) + ((_k & 3) * 2) + ((_k >> 2) & 1);        \
        _p[0]  = f2tf32((v).x);  _p[8]  = f2tf32((v).y);                       \
        _p[16] = f2tf32((v).z);  _p[24] = f2tf32((v).w);                       \
    } while (0)

    // ---- prologue: stage 0 ----
    {
        const float* Ag = A + (size_t)bm * K;
        const float* Bg = B + bn;
#pragma unroll
        for (int j = 0; j < 4; j++) {
            int ia = tid + j * 256;
            pa[j] = *(const float4*)(Ag + (size_t)(ia >> 3) * K + (ia & 7) * 4);
            pb[j] = *(const float4*)(Bg + (size_t)(ia >> 5) * N + (ia & 31) * 4);
        }
#pragma unroll
        for (int j = 0; j < 4; j++) {
            int ia = tid + j * 256;
            STORE_A_PK(As, ia, pa[j]);
            STORE_B_PK(Bs, ia, pb[j]);
        }
    }
    __syncthreads();

    for (int s = 0; s < nst; s++) {
        // ---- prefetch next stage into registers ----
        if (s + 1 < nst) {
            const float* Ag = A + (size_t)bm * K + (s + 1) * BK;
            const float* Bg = B + (size_t)(s + 1) * BK * N + bn;
#pragma unroll
            for (int j = 0; j < 4; j++) {
                int ia = tid + j * 256;
                pa[j] = *(const float4*)(Ag + (size_t)(ia >> 3) * K + (ia & 7) * 4);
                pb[j] = *(const float4*)(Bg + (size_t)(ia >> 5) * N + (ia & 31) * 4);
            }
        }

        // ---- compute on current buffer ----
        {
            const float* Ab = As + (s & 1) * ASTG;
            const float* Bb = Bs + (s & 1) * BSTG;
#pragma unroll
            for (int kk = 0; kk < 4; kk++) {
                uint32_t af[2][4], bf[8][2];
#pragma unroll
                for (int mt = 0; mt < 2; mt++) {
                    int f = wm * 2 + mt;
                    float4 av = *(const float4*)&Ab[(f * 4 + kk) * APITCH + lane * 4];
                    af[mt][0] = __float_as_uint(av.x);
                    af[mt][1] = __float_as_uint(av.y);
                    af[mt][2] = __float_as_uint(av.z);
                    af[mt][3] = __float_as_uint(av.w);
                }
#pragma unroll
                for (int nt = 0; nt < 8; nt++) {
                    int nf = wn * 8 + nt;
                    float2 bv = *(const float2*)&Bb[(kk * 16 + nf) * BPITCH + lane * 2];
                    bf[nt][0] = __float_as_uint(bv.x);
                    bf[nt][1] = __float_as_uint(bv.y);
                }
#pragma unroll
                for (int mt = 0; mt < 2; mt++)
#pragma unroll
                    for (int nt = 0; nt < 8; nt++)
                        MMA_TF32(acc[mt][nt], af[mt][0], af[mt][1], af[mt][2], af[mt][3],
                                 bf[nt][0], bf[nt][1]);
            }
        }

        // ---- store prefetched stage into the other buffer ----
        if (s + 1 < nst) {
            float* Ad = As + ((s + 1) & 1) * ASTG;
            float* Bd = Bs + ((s + 1) & 1) * BSTG;
#pragma unroll
            for (int j = 0; j < 4; j++) {
                int ia = tid + j * 256;
                STORE_A_PK(Ad, ia, pa[j]);
                STORE_B_PK(Bd, ia, pb[j]);
            }
        }
        __syncthreads();
    }

    // ---- epilogue: stage through smem (overlays drained buffers) ----
#pragma unroll
    for (int mt = 0; mt < 2; mt++)
#pragma unroll
        for (int nt = 0; nt < 8; nt++) {
            int r0 = wm * 32 + mt * 16 + (lane >> 2);
            int c0 = wn * 64 + nt * 8 + (lane & 3) * 2;
            *(float2*)&Cs[r0 * PADC + c0]       = make_float2(acc[mt][nt][0], acc[mt][nt][1]);
            *(float2*)&Cs[(r0 + 8) * PADC + c0] = make_float2(acc[mt][nt][2], acc[mt][nt][3]);
        }
    __syncthreads();

    if (rope) {
#pragma unroll
        for (int j = 0; j < 32; j++) {
            int idx = tid + j * 256;       // 128 rows * 64 pairs
            int row = idx >> 6, p = idx & 63;
            int t = (bm + row) & (TT - 1);
            float2 cs = g_cs[t][p];
            float a0 = Cs[row * PADC + p];
            float a1 = Cs[row * PADC + p + 64];
            float* crow = C + (size_t)(bm + row) * N + bn;
            crow[p]      = a0 * cs.x + a1 * cs.y;   // reversed rotation (R9)
            crow[p + 64] = a1 * cs.x - a0 * cs.y;
        }
    } else {
#pragma unroll
        for (int j = 0; j < 16; j++) {
            int idx = tid + j * 256;       // 128 rows * 32 float4
            int row = idx >> 5, c4 = idx & 31;
            *(float4*)(C + (size_t)(bm + row) * N + bn + c4 * 4) =
                *(float4*)&Cs[row * PADC + c4 * 4];
        }
    }
}

// ---------------------------------------------------------------------------
// Attention (causal, GQA) on tf32 tensor cores. R14-EXACT (validated 2415us).
// ---------------------------------------------------------------------------
__global__ __launch_bounds__(256) void attn_mma_kernel(
    const float* __restrict__ q, const float* __restrict__ k,
    const float* __restrict__ v, float* __restrict__ o)
{
    extern __shared__ float smem[];
    float* sQ = smem;
    float* sK = sQ + 128 * QP;
    float* sV = sK + 64 * KVP;
    float* sP = sV + 64 * KVP;

    const int qi = blockIdx.x;
    const int bh = blockIdx.y;
    const int b  = bh / HH;
    const int h  = bh % HH;
    const int kvh = h / GG;
    const int t0 = qi * 128;

    const int tid  = threadIdx.x;
    const int warp = tid >> 5;
    const int lane = tid & 31;
    const int lq   = lane >> 2;
    const int lr   = lane & 3;

    const float scale = 0.08838834764831845f;

#pragma unroll
    for (int j = 0; j < 16; j++) {
        int idx4 = tid + j * 256;
        int r = idx4 >> 5, c4 = idx4 & 31;
        float4 qv = *(const float4*)(q + (size_t)(b * TT + t0 + r) * (HH * DD) + h * DD + c4 * 4);
        *(float4*)&sQ[r * QP + c4 * 4] =
            make_float4(f2tf32(qv.x * scale), f2tf32(qv.y * scale),
                        f2tf32(qv.z * scale), f2tf32(qv.w * scale));
    }

    float m0 = -1e30f, m1 = -1e30f, l0 = 0.f, l1 = 0.f;
    float O[16][4];
#pragma unroll
    for (int nt = 0; nt < 16; nt++)
#pragma unroll
        for (int c = 0; c < 4; c++) O[nt][c] = 0.f;

    const int row0 = warp * 16 + lq;
    const int nkt  = qi * 2 + 2;

    for (int jt = 0; jt < nkt; jt++) {
        __syncthreads();
#pragma unroll
        for (int j = 0; j < 8; j++) {
            int idx4 = tid + j * 256;
            int r = idx4 >> 5, c4 = idx4 & 31;
            size_t gofs = (size_t)(b * TT + jt * 64 + r) * (KVH * DD) + kvh * DD + c4 * 4;
            float4 kv = *(const float4*)(k + gofs);
            float4 vv = *(const float4*)(v + gofs);
            *(float4*)&sK[r * KVP + c4 * 4] =
                make_float4(f2tf32(kv.x), f2tf32(kv.y), f2tf32(kv.z), f2tf32(kv.w));
            *(float4*)&sV[r * KVP + c4 * 4] =
                make_float4(f2tf32(vv.x), f2tf32(vv.y), f2tf32(vv.z), f2tf32(vv.w));
        }
        __syncthreads();

        float sacc[8][4];
#pragma unroll
        for (int nt = 0; nt < 8; nt++)
#pragma unroll
            for (int c = 0; c < 4; c++) sacc[nt][c] = 0.f;

#pragma unroll
        for (int ks = 0; ks < 16; ks++) {
            const int k0 = ks * 8;
            const float* ap = sQ + (size_t)row0 * QP + k0 + lr;
            uint32_t a0 = __float_as_uint(ap[0]);
            uint32_t a1 = __float_as_uint(ap[8 * QP]);
            uint32_t a2 = __float_as_uint(ap[4]);
            uint32_t a3 = __float_as_uint(ap[8 * QP + 4]);
#pragma unroll
            for (int nt = 0; nt < 8; nt++) {
                const float* bp = sK + (size_t)(nt * 8 + lq) * KVP + k0 + lr;
                uint32_t b0 = __float_as_uint(bp[0]);
                uint32_t b1 = __float_as_uint(bp[4]);
                MMA_TF32(sacc[nt], a0, a1, a2, a3, b0, b1);
            }
        }

        const int kbase = jt * 64;
        if (kbase + 63 > t0 + warp * 16) {
            int rg0 = t0 + row0, rg1 = rg0 + 8;
#pragma unroll
            for (int nt = 0; nt < 8; nt++) {
                int cg = kbase + nt * 8 + 2 * lr;
                if (cg     > rg0) sacc[nt][0] = -1e30f;
                if (cg + 1 > rg0) sacc[nt][1] = -1e30f;
                if (cg     > rg1) sacc[nt][2] = -1e30f;
                if (cg + 1 > rg1) sacc[nt][3] = -1e30f;
            }
        }

        float mx0 = -1e30f, mx1 = -1e30f;
#pragma unroll
        for (int nt = 0; nt < 8; nt++) {
            mx0 = fmaxf(mx0, fmaxf(sacc[nt][0], sacc[nt][1]));
            mx1 = fmaxf(mx1, fmaxf(sacc[nt][2], sacc[nt][3]));
        }
        mx0 = fmaxf(mx0, __shfl_xor_sync(0xffffffffu, mx0, 1));
        mx0 = fmaxf(mx0, __shfl_xor_sync(0xffffffffu, mx0, 2));
        mx1 = fmaxf(mx1, __shfl_xor_sync(0xffffffffu, mx1, 1));
        mx1 = fmaxf(mx1, __shfl_xor_sync(0xffffffffu, mx1, 2));

        float mn0 = fmaxf(m0, mx0), mn1 = fmaxf(m1, mx1);
        float f0 = __expf(m0 - mn0), f1 = __expf(m1 - mn1);

        float rs0 = 0.f, rs1 = 0.f;
#pragma unroll
        for (int nt = 0; nt < 8; nt++) {
            float p0 = __expf(sacc[nt][0] - mn0);
            float p1 = __expf(sacc[nt][1] - mn0);
            float p2 = __expf(sacc[nt][2] - mn1);
            float p3 = __expf(sacc[nt][3] - mn1);
            rs0 += p0 + p1; rs1 += p2 + p3;
            float* pp = sP + (size_t)row0 * PP + nt * 8 + 2 * lr;
            *(float2*)pp            = make_float2(f2tf32(p0), f2tf32(p1));
            *(float2*)(pp + 8 * PP) = make_float2(f2tf32(p2), f2tf32(p3));
        }
        rs0 += __shfl_xor_sync(0xffffffffu, rs0, 1);
        rs0 += __shfl_xor_sync(0xffffffffu, rs0, 2);
        rs1 += __shfl_xor_sync(0xffffffffu, rs1, 1);
        rs1 += __shfl_xor_sync(0xffffffffu, rs1, 2);

        l0 = l0 * f0 + rs0;  m0 = mn0;
        l1 = l1 * f1 + rs1;  m1 = mn1;

#pragma unroll
        for (int nt = 0; nt < 16; nt++) {
            O[nt][0] *= f0; O[nt][1] *= f0;
            O[nt][2] *= f1; O[nt][3] *= f1;
        }
        __syncwarp();

#pragma unroll
        for (int ks = 0; ks < 8; ks++) {
            const int k0 = ks * 8;
            const float* ap = sP + (size_t)row0 * PP + k0 + lr;
            uint32_t a0 = __float_as_uint(ap[0]);
            uint32_t a1 = __float_as_uint(ap[8 * PP]);
            uint32_t a2 = __float_as_uint(ap[4]);
            uint32_t a3 = __float_as_uint(ap[8 * PP + 4]);
#pragma unroll
            for (int nt = 0; nt < 16; nt++) {
                const float* bp = sV + (size_t)(k0 + lr) * KVP + nt * 8 + lq;
                uint32_t b0 = __float_as_uint(bp[0]);
                uint32_t b1 = __float_as_uint(bp[4 * KVP]);
                MMA_TF32(O[nt], a0, a1, a2, a3, b0, b1);
            }
        }
    }

    float il0 = 1.0f / l0, il1 = 1.0f / l1;
    float* d0 = o + (size_t)(b * TT + t0 + row0) * (HH * DD) + h * DD;
    float* d1 = d0 + 8 * (HH * DD);
#pragma unroll
    for (int nt = 0; nt < 16; nt++) {
        int c0 = nt * 8 + 2 * lr;
        *(float2*)(d0 + c0) = make_float2(O[nt][0] * il0, O[nt][1] * il0);
        *(float2*)(d1 + c0) = make_float2(O[nt][2] * il1, O[nt][3] * il1);
    }
}

// ---------------------------------------------------------------------------
extern "C" void kernel_launch(void* const* d_in, const int* in_sizes, int n_in,
                              void* d_out, int out_size)
{
    const float *x, *Wq, *Wk, *Wv, *Wo;
    if (in_sizes[0] == BB * TT * CC) {
        x  = (const float*)d_in[0];
        Wq = (const float*)d_in[1];
        Wk = (const float*)d_in[2];
        Wv = (const float*)d_in[3];
        Wo = (const float*)d_in[4];
    } else {
        Wk = (const float*)d_in[0];
        Wo = (const float*)d_in[1];
        Wq = (const float*)d_in[2];
        Wv = (const float*)d_in[3];
        x  = (const float*)d_in[4];
    }
    float* out = (float*)d_out;

    float *q, *k, *v, *ao;
    cudaGetSymbolAddress((void**)&q,  g_q);
    cudaGetSymbolAddress((void**)&k,  g_k);
    cudaGetSymbolAddress((void**)&v,  g_v);
    cudaGetSymbolAddress((void**)&ao, g_ao);

    init_tables_kernel<<<(TT * 64 + 255) / 256, 256>>>();

    // smem: max(packed buffers 2*(ASTG+BSTG), C staging 128*PADC) floats
    int g_floats = 2 * (ASTG + BSTG);
    int c_floats = 128 * PADC;
    const int gemm_smem = (g_floats > c_floats ? g_floats : c_floats) * 4;  // 67584 B
    cudaFuncSetAttribute(gemm_tf32_rope_kernel,
                         cudaFuncAttributeMaxDynamicSharedMemorySize, gemm_smem);

    dim3 blk(256);
    gemm_tf32_rope_kernel<<<dim3(HH*DD/128,  MROWS/128), blk, gemm_smem>>>(x, Wq, q, MROWS, HH*DD,  CC, 1);
    gemm_tf32_rope_kernel<<<dim3(KVH*DD/128, MROWS/128), blk, gemm_smem>>>(x, Wk, k, MROWS, KVH*DD, CC, 1);
    gemm_tf32_rope_kernel<<<dim3(KVH*DD/128, MROWS/128), blk, gemm_smem>>>(x, Wv, v, MROWS, KVH*DD, CC, 0);

    {
        const int attn_smem = (128*QP + 64*KVP + 64*KVP + 128*PP) * 4;  // 169984 B
        cudaFuncSetAttribute(attn_mma_kernel,
                             cudaFuncAttributeMaxDynamicSharedMemorySize, attn_smem);
        attn_mma_kernel<<<dim3(TT/128, BB*HH), 256, attn_smem>>>(q, k, v, ao);
    }

    gemm_tf32_rope_kernel<<<dim3(CC/128, MROWS/128), blk, gemm_smem>>>(ao, Wo, out, MROWS, CC, CC, 0);
}

// round 17
// speedup vs baseline: 3.9490x; 1.1504x over previous
#include <cuda_runtime.h>
#include <math.h>
#include <cstdint>

// Problem constants
#define BB 4
#define TT 2048
#define CC 2048
#define HH 16
#define KVH 4
#define GG 4
#define DD 128
#define MROWS (BB*TT)          // 8192

#define BK 32
#define PADA 36     // GEMM A smem row pitch (words)
#define PADB 136    // GEMM B smem row pitch (words)
#define PADC 132    // C staging pitch (words)

#define QP 132      // attn Q pitch
#define KVP 132     // attn K/V pitch
#define PP 68       // attn P pitch

// ---------------- scratch (device globals; allocation is forbidden) --------
__device__ float  g_q  [(size_t)MROWS * (HH*DD)];
__device__ float  g_k  [(size_t)MROWS * (KVH*DD)];
__device__ float  g_v  [(size_t)MROWS * (KVH*DD)];
__device__ float  g_ao [(size_t)MROWS * (HH*DD)];   // attention out (tf32-rounded)
__device__ float  g_xt [(size_t)MROWS * CC];        // tf32-rounded x
__device__ float  g_wqt[(size_t)CC * (HH*DD)];
__device__ float  g_wkt[(size_t)CC * (KVH*DD)];
__device__ float  g_wvt[(size_t)CC * (KVH*DD)];
__device__ float  g_wot[(size_t)CC * CC];
__device__ float2 g_cs[TT][64];                     // cos/sin(t * 10000^(-p/64))

// ---------------------------------------------------------------------------
__global__ void init_tables_kernel()
{
    int idx = blockIdx.x * blockDim.x + threadIdx.x;   // t*64 + p
    if (idx >= TT * 64) return;
    int t = idx >> 6;
    int p = idx & 63;

    double ex   = (double)p / 64.0;
    float  invf = (float)pow(10000.0, -ex);
    float  ang  = (float)t * invf;
    double c, s;
    sincos((double)ang, &c, &s);
    g_cs[t][p] = make_float2((float)c, (float)s);
}

__device__ __forceinline__ float f2tf32(float x)
{
    uint32_t u;
    asm("cvt.rna.tf32.f32 %0, %1;" : "=r"(u) : "f"(x));
    return __uint_as_float(u);
}

// elementwise tf32 rounding pass (float4 vectorized)
__global__ void conv_tf32_kernel(const float* __restrict__ in,
                                 float* __restrict__ out, int n4)
{
    int i = blockIdx.x * blockDim.x + threadIdx.x;
    if (i >= n4) return;
    float4 v = ((const float4*)in)[i];
    ((float4*)out)[i] = make_float4(f2tf32(v.x), f2tf32(v.y), f2tf32(v.z), f2tf32(v.w));
}

#define MMA_TF32(ACC, A0, A1, A2, A3, B0, B1)                                  \
    asm volatile(                                                              \
        "mma.sync.aligned.m16n8k8.row.col.f32.tf32.tf32.f32 "                  \
        "{%0,%1,%2,%3}, {%4,%5,%6,%7}, {%8,%9}, {%0,%1,%2,%3};"                \
        : "+f"((ACC)[0]), "+f"((ACC)[1]), "+f"((ACC)[2]), "+f"((ACC)[3])       \
        : "r"(A0), "r"(A1), "r"(A2), "r"(A3), "r"(B0), "r"(B1))

#define CP_ASYNC16(saddr, gptr) \
    asm volatile("cp.async.ca.shared.global [%0], [%1], 16;" :: "r"(saddr), "l"(gptr))
#define CP_COMMIT() asm volatile("cp.async.commit_group;" ::: "memory")
#define CP_WAIT1()  asm volatile("cp.async.wait_group 1;" ::: "memory")
#define CP_WAIT0()  asm volatile("cp.async.wait_group 0;" ::: "memory")

__device__ __forceinline__ uint32_t smem_u32(const void* p) {
    uint32_t a;
    asm("{ .reg .u64 t; cvta.to.shared.u64 t, %1; cvt.u32.u64 %0, t; }"
        : "=r"(a) : "l"(p));
    return a;
}

// ---------------------------------------------------------------------------
// tf32 tensor-core GEMM v3: inputs PRE-CONVERTED to tf32 in global.
// cp.async double-buffered (no prefetch regs, no convert ALU), linear
// R11 layouts (A [m][k] pitch 36, B [k][n] pitch 136), 128x128 tile, BK=32,
// 8 warps 4x2, __launch_bounds__(256,2) -> 2 CTA/SM.
// Fused REVERSED-RoPE epilogue (R9-validated), arithmetic identical to R16.
// ---------------------------------------------------------------------------
__global__ __launch_bounds__(256, 2) void gemm_cp_rope_kernel(
    const float* __restrict__ A, const float* __restrict__ B,
    float* __restrict__ C, int M, int N, int K, int rope)
{
    extern __shared__ float sm[];
    float* As = sm;                     // 2 * 128 * PADA = 9216 floats
    float* Bs = sm + 2 * 128 * PADA;    // 2 * 32  * PADB = 8704 floats
    float* Cs = sm;                     // epilogue overlay

    const int tid  = threadIdx.x;
    const int lane = tid & 31;
    const int warp = tid >> 5;
    const int wm = warp >> 1;           // 0..3  (M)
    const int wn = warp & 1;            // 0..1  (N)
    const int bm = blockIdx.y * 128;
    const int bn = blockIdx.x * 128;

    const int nst = K / BK;
    const uint32_t sAu = smem_u32(As);
    const uint32_t sBu = smem_u32(Bs);

    float acc[2][8][4];
#pragma unroll
    for (int mt = 0; mt < 2; mt++)
#pragma unroll
        for (int nt = 0; nt < 8; nt++)
#pragma unroll
            for (int c = 0; c < 4; c++) acc[mt][nt][c] = 0.f;

    // ---- async stage issue: 4 A-chunks + 4 B-chunks per thread ----
#define ISSUE_STAGE(s) do {                                                    \
        const float* Ag = A + (size_t)bm * K + (s) * BK;                       \
        const float* Bg = B + (size_t)(s) * BK * N + bn;                       \
        uint32_t ab = sAu + (((s) & 1) * 128 * PADA) * 4;                      \
        uint32_t bb = sBu + (((s) & 1) * 32 * PADB) * 4;                       \
        _Pragma("unroll")                                                      \
        for (int j = 0; j < 4; j++) {                                          \
            int ia = tid + j * 256;                                            \
            int r = ia >> 3, c8 = ia & 7;                                      \
            CP_ASYNC16(ab + (uint32_t)(r * PADA + c8 * 4) * 4,                 \
                       Ag + (size_t)r * K + c8 * 4);                           \
            int kk = ia >> 5, n0 = (ia & 31) * 4;                              \
            CP_ASYNC16(bb + (uint32_t)(kk * PADB + n0) * 4,                    \
                       Bg + (size_t)kk * N + n0);                              \
        }                                                                      \
        CP_COMMIT();                                                           \
    } while (0)

    ISSUE_STAGE(0);

    for (int s = 0; s < nst; s++) {
        if (s + 1 < nst) { ISSUE_STAGE(s + 1); CP_WAIT1(); }
        else             { CP_WAIT0(); }
        __syncthreads();

        // ---- compute on current buffer (R11 fragment pattern, no convert) --
        {
            const float* Ab = As + (s & 1) * 128 * PADA;
            const float* Bb = Bs + (s & 1) * 32 * PADB;
#pragma unroll
            for (int kk = 0; kk < 4; kk++) {
                uint32_t af[2][4], bf[8][2];
                const int k0 = kk * 8;
                const int arow = wm * 32 + (lane >> 2);
                const int acol = k0 + (lane & 3);
#pragma unroll
                for (int mt = 0; mt < 2; mt++) {
                    const float* ap = Ab + (size_t)(arow + mt * 16) * PADA + acol;
                    af[mt][0] = __float_as_uint(ap[0]);
                    af[mt][1] = __float_as_uint(ap[8 * PADA]);
                    af[mt][2] = __float_as_uint(ap[4]);
                    af[mt][3] = __float_as_uint(ap[8 * PADA + 4]);
                }
                const int bk  = k0 + (lane & 3);
                const int bn0 = wn * 64 + (lane >> 2);
#pragma unroll
                for (int nt = 0; nt < 8; nt++) {
                    const float* bp = Bb + (size_t)bk * PADB + bn0 + nt * 8;
                    bf[nt][0] = __float_as_uint(bp[0]);
                    bf[nt][1] = __float_as_uint(bp[4 * PADB]);
                }
#pragma unroll
                for (int mt = 0; mt < 2; mt++)
#pragma unroll
                    for (int nt = 0; nt < 8; nt++)
                        MMA_TF32(acc[mt][nt], af[mt][0], af[mt][1], af[mt][2], af[mt][3],
                                 bf[nt][0], bf[nt][1]);
            }
        }
        __syncthreads();   // buffer consumed before next overwrite
    }

    // ---- epilogue: stage through smem (overlay; all copies drained) ----
#pragma unroll
    for (int mt = 0; mt < 2; mt++)
#pragma unroll
        for (int nt = 0; nt < 8; nt++) {
            int r0 = wm * 32 + mt * 16 + (lane >> 2);
            int c0 = wn * 64 + nt * 8 + (lane & 3) * 2;
            *(float2*)&Cs[r0 * PADC + c0]       = make_float2(acc[mt][nt][0], acc[mt][nt][1]);
            *(float2*)&Cs[(r0 + 8) * PADC + c0] = make_float2(acc[mt][nt][2], acc[mt][nt][3]);
        }
    __syncthreads();

    if (rope) {
#pragma unroll
        for (int j = 0; j < 32; j++) {
            int idx = tid + j * 256;       // 128 rows * 64 pairs
            int row = idx >> 6, p = idx & 63;
            int t = (bm + row) & (TT - 1);
            float2 cs = g_cs[t][p];
            float a0 = Cs[row * PADC + p];
            float a1 = Cs[row * PADC + p + 64];
            float* crow = C + (size_t)(bm + row) * N + bn;
            crow[p]      = a0 * cs.x + a1 * cs.y;   // reversed rotation (R9)
            crow[p + 64] = a1 * cs.x - a0 * cs.y;
        }
    } else {
#pragma unroll
        for (int j = 0; j < 16; j++) {
            int idx = tid + j * 256;       // 128 rows * 32 float4
            int row = idx >> 5, c4 = idx & 31;
            *(float4*)(C + (size_t)(bm + row) * N + bn + c4 * 4) =
                *(float4*)&Cs[row * PADC + c4 * 4];
        }
    }
}

// ---------------------------------------------------------------------------
// Attention (causal, GQA) on tf32 tensor cores. R14-exact except the
// epilogue rounds outputs to tf32 (feeds the pre-converted Wo GEMM; the
// rounding site is identical to the old GEMM store path -> bit-identical).
// ---------------------------------------------------------------------------
__global__ __launch_bounds__(256) void attn_mma_kernel(
    const float* __restrict__ q, const float* __restrict__ k,
    const float* __restrict__ v, float* __restrict__ o)
{
    extern __shared__ float smem[];
    float* sQ = smem;
    float* sK = sQ + 128 * QP;
    float* sV = sK + 64 * KVP;
    float* sP = sV + 64 * KVP;

    const int qi = blockIdx.x;
    const int bh = blockIdx.y;
    const int b  = bh / HH;
    const int h  = bh % HH;
    const int kvh = h / GG;
    const int t0 = qi * 128;

    const int tid  = threadIdx.x;
    const int warp = tid >> 5;
    const int lane = tid & 31;
    const int lq   = lane >> 2;
    const int lr   = lane & 3;

    const float scale = 0.08838834764831845f;

#pragma unroll
    for (int j = 0; j < 16; j++) {
        int idx4 = tid + j * 256;
        int r = idx4 >> 5, c4 = idx4 & 31;
        float4 qv = *(const float4*)(q + (size_t)(b * TT + t0 + r) * (HH * DD) + h * DD + c4 * 4);
        *(float4*)&sQ[r * QP + c4 * 4] =
            make_float4(f2tf32(qv.x * scale), f2tf32(qv.y * scale),
                        f2tf32(qv.z * scale), f2tf32(qv.w * scale));
    }

    float m0 = -1e30f, m1 = -1e30f, l0 = 0.f, l1 = 0.f;
    float O[16][4];
#pragma unroll
    for (int nt = 0; nt < 16; nt++)
#pragma unroll
        for (int c = 0; c < 4; c++) O[nt][c] = 0.f;

    const int row0 = warp * 16 + lq;
    const int nkt  = qi * 2 + 2;

    for (int jt = 0; jt < nkt; jt++) {
        __syncthreads();
#pragma unroll
        for (int j = 0; j < 8; j++) {
            int idx4 = tid + j * 256;
            int r = idx4 >> 5, c4 = idx4 & 31;
            size_t gofs = (size_t)(b * TT + jt * 64 + r) * (KVH * DD) + kvh * DD + c4 * 4;
            float4 kv = *(const float4*)(k + gofs);
            float4 vv = *(const float4*)(v + gofs);
            *(float4*)&sK[r * KVP + c4 * 4] =
                make_float4(f2tf32(kv.x), f2tf32(kv.y), f2tf32(kv.z), f2tf32(kv.w));
            *(float4*)&sV[r * KVP + c4 * 4] =
                make_float4(f2tf32(vv.x), f2tf32(vv.y), f2tf32(vv.z), f2tf32(vv.w));
        }
        __syncthreads();

        float sacc[8][4];
#pragma unroll
        for (int nt = 0; nt < 8; nt++)
#pragma unroll
            for (int c = 0; c < 4; c++) sacc[nt][c] = 0.f;

#pragma unroll
        for (int ks = 0; ks < 16; ks++) {
            const int k0 = ks * 8;
            const float* ap = sQ + (size_t)row0 * QP + k0 + lr;
            uint32_t a0 = __float_as_uint(ap[0]);
            uint32_t a1 = __float_as_uint(ap[8 * QP]);
            uint32_t a2 = __float_as_uint(ap[4]);
            uint32_t a3 = __float_as_uint(ap[8 * QP + 4]);
#pragma unroll
            for (int nt = 0; nt < 8; nt++) {
                const float* bp = sK + (size_t)(nt * 8 + lq) * KVP + k0 + lr;
                uint32_t b0 = __float_as_uint(bp[0]);
                uint32_t b1 = __float_as_uint(bp[4]);
                MMA_TF32(sacc[nt], a0, a1, a2, a3, b0, b1);
            }
        }

        const int kbase = jt * 64;
        if (kbase + 63 > t0 + warp * 16) {
            int rg0 = t0 + row0, rg1 = rg0 + 8;
#pragma unroll
            for (int nt = 0; nt < 8; nt++) {
                int cg = kbase + nt * 8 + 2 * lr;
                if (cg     > rg0) sacc[nt][0] = -1e30f;
                if (cg + 1 > rg0) sacc[nt][1] = -1e30f;
                if (cg     > rg1) sacc[nt][2] = -1e30f;
                if (cg + 1 > rg1) sacc[nt][3] = -1e30f;
            }
        }

        float mx0 = -1e30f, mx1 = -1e30f;
#pragma unroll
        for (int nt = 0; nt < 8; nt++) {
            mx0 = fmaxf(mx0, fmaxf(sacc[nt][0], sacc[nt][1]));
            mx1 = fmaxf(mx1, fmaxf(sacc[nt][2], sacc[nt][3]));
        }
        mx0 = fmaxf(mx0, __shfl_xor_sync(0xffffffffu, mx0, 1));
        mx0 = fmaxf(mx0, __shfl_xor_sync(0xffffffffu, mx0, 2));
        mx1 = fmaxf(mx1, __shfl_xor_sync(0xffffffffu, mx1, 1));
        mx1 = fmaxf(mx1, __shfl_xor_sync(0xffffffffu, mx1, 2));

        float mn0 = fmaxf(m0, mx0), mn1 = fmaxf(m1, mx1);
        float f0 = __expf(m0 - mn0), f1 = __expf(m1 - mn1);

        float rs0 = 0.f, rs1 = 0.f;
#pragma unroll
        for (int nt = 0; nt < 8; nt++) {
            float p0 = __expf(sacc[nt][0] - mn0);
            float p1 = __expf(sacc[nt][1] - mn0);
            float p2 = __expf(sacc[nt][2] - mn1);
            float p3 = __expf(sacc[nt][3] - mn1);
            rs0 += p0 + p1; rs1 += p2 + p3;
            float* pp = sP + (size_t)row0 * PP + nt * 8 + 2 * lr;
            *(float2*)pp            = make_float2(f2tf32(p0), f2tf32(p1));
            *(float2*)(pp + 8 * PP) = make_float2(f2tf32(p2), f2tf32(p3));
        }
        rs0 += __shfl_xor_sync(0xffffffffu, rs0, 1);
        rs0 += __shfl_xor_sync(0xffffffffu, rs0, 2);
        rs1 += __shfl_xor_sync(0xffffffffu, rs1, 1);
        rs1 += __shfl_xor_sync(0xffffffffu, rs1, 2);

        l0 = l0 * f0 + rs0;  m0 = mn0;
        l1 = l1 * f1 + rs1;  m1 = mn1;

#pragma unroll
        for (int nt = 0; nt < 16; nt++) {
            O[nt][0] *= f0; O[nt][1] *= f0;
            O[nt][2] *= f1; O[nt][3] *= f1;
        }
        __syncwarp();

#pragma unroll
        for (int ks = 0; ks < 8; ks++) {
            const int k0 = ks * 8;
            const float* ap = sP + (size_t)row0 * PP + k0 + lr;
            uint32_t a0 = __float_as_uint(ap[0]);
            uint32_t a1 = __float_as_uint(ap[8 * PP]);
            uint32_t a2 = __float_as_uint(ap[4]);
            uint32_t a3 = __float_as_uint(ap[8 * PP + 4]);
#pragma unroll
            for (int nt = 0; nt < 16; nt++) {
                const float* bp = sV + (size_t)(k0 + lr) * KVP + nt * 8 + lq;
                uint32_t b0 = __float_as_uint(bp[0]);
                uint32_t b1 = __float_as_uint(bp[4 * KVP]);
                MMA_TF32(O[nt], a0, a1, a2, a3, b0, b1);
            }
        }
    }

    float il0 = 1.0f / l0, il1 = 1.0f / l1;
    float* d0 = o + (size_t)(b * TT + t0 + row0) * (HH * DD) + h * DD;
    float* d1 = d0 + 8 * (HH * DD);
#pragma unroll
    for (int nt = 0; nt < 16; nt++) {
        int c0 = nt * 8 + 2 * lr;
        // tf32-round at the (former GEMM-store) rounding site -> bit-identical
        *(float2*)(d0 + c0) = make_float2(f2tf32(O[nt][0] * il0), f2tf32(O[nt][1] * il0));
        *(float2*)(d1 + c0) = make_float2(f2tf32(O[nt][2] * il1), f2tf32(O[nt][3] * il1));
    }
}

// ---------------------------------------------------------------------------
extern "C" void kernel_launch(void* const* d_in, const int* in_sizes, int n_in,
                              void* d_out, int out_size)
{
    const float *x, *Wq, *Wk, *Wv, *Wo;
    if (in_sizes[0] == BB * TT * CC) {
        x  = (const float*)d_in[0];
        Wq = (const float*)d_in[1];
        Wk = (const float*)d_in[2];
        Wv = (const float*)d_in[3];
        Wo = (const float*)d_in[4];
    } else {
        Wk = (const float*)d_in[0];
        Wo = (const float*)d_in[1];
        Wq = (const float*)d_in[2];
        Wv = (const float*)d_in[3];
        x  = (const float*)d_in[4];
    }
    float* out = (float*)d_out;

    float *q, *k, *v, *ao, *xt, *wqt, *wkt, *wvt, *wot;
    cudaGetSymbolAddress((void**)&q,   g_q);
    cudaGetSymbolAddress((void**)&k,   g_k);
    cudaGetSymbolAddress((void**)&v,   g_v);
    cudaGetSymbolAddress((void**)&ao,  g_ao);
    cudaGetSymbolAddress((void**)&xt,  g_xt);
    cudaGetSymbolAddress((void**)&wqt, g_wqt);
    cudaGetSymbolAddress((void**)&wkt, g_wkt);
    cudaGetSymbolAddress((void**)&wvt, g_wvt);
    cudaGetSymbolAddress((void**)&wot, g_wot);

    init_tables_kernel<<<(TT * 64 + 255) / 256, 256>>>();

    // pre-convert inputs to tf32 (same cvt.rna site as before -> canary holds)
    {
        int n;
        n = MROWS * CC / 4;        conv_tf32_kernel<<<(n + 255) / 256, 256>>>(x,  xt,  n);
        n = CC * (HH*DD) / 4;      conv_tf32_kernel<<<(n + 255) / 256, 256>>>(Wq, wqt, n);
        n = CC * (KVH*DD) / 4;     conv_tf32_kernel<<<(n + 255) / 256, 256>>>(Wk, wkt, n);
        n = CC * (KVH*DD) / 4;     conv_tf32_kernel<<<(n + 255) / 256, 256>>>(Wv, wvt, n);
        n = CC * CC / 4;           conv_tf32_kernel<<<(n + 255) / 256, 256>>>(Wo, wot, n);
    }

    const int gemm_smem = (2*128*PADA + 2*32*PADB) * 4;   // 71680 B (C overlay smaller)
    cudaFuncSetAttribute(gemm_cp_rope_kernel,
                         cudaFuncAttributeMaxDynamicSharedMemorySize, gemm_smem);

    dim3 blk(256);
    gemm_cp_rope_kernel<<<dim3(HH*DD/128,  MROWS/128), blk, gemm_smem>>>(xt, wqt, q, MROWS, HH*DD,  CC, 1);
    gemm_cp_rope_kernel<<<dim3(KVH*DD/128, MROWS/128), blk, gemm_smem>>>(xt, wkt, k, MROWS, KVH*DD, CC, 1);
    gemm_cp_rope_kernel<<<dim3(KVH*DD/128, MROWS/128), blk, gemm_smem>>>(xt, wvt, v, MROWS, KVH*DD, CC, 0);

    {
        const int attn_smem = (128*QP + 64*KVP + 64*KVP + 128*PP) * 4;  // 169984 B
        cudaFuncSetAttribute(attn_mma_kernel,
                             cudaFuncAttributeMaxDynamicSharedMemorySize, attn_smem);
        attn_mma_kernel<<<dim3(TT/128, BB*HH), 256, attn_smem>>>(q, k, v, ao);
    }

    gemm_cp_rope_kernel<<<dim3(CC/128, MROWS/128), blk, gemm_smem>>>(ao, wot, out, MROWS, CC, CC, 0);
}